// round 6
// baseline (speedup 1.0000x reference)
#include <cuda_runtime.h>
#include <cuda_bf16.h>
#include <math.h>

#define N_NODES 100000
#define IN_C    128
#define HEADS   4
#define OUT_C   64
#define HC      256           // HEADS*OUT_C
#define NE      1600000
#define ET      (NE + N_NODES)   // edges + self loops = 1,700,000
#define NEG_SLOPE 0.2f
#define BN_EPS  1e-5f

// ---------------- scratch (device globals; no allocations allowed) ----------
__device__ float  g_h[(size_t)N_NODES * HC];     // projected features, 102.4 MB
__device__ float4 g_asrc[N_NODES];               // per-node src-attn dots (4 heads)
__device__ float4 g_adst[N_NODES];               // per-node dst-attn dots (4 heads)
__device__ int    g_deg[N_NODES];
__device__ int    g_off[N_NODES + 1];
__device__ int    g_cur[N_NODES];
__device__ int    g_srcid[ET];
__device__ int    g_bsum[128];
__device__ int    g_bbase[128];
__device__ float  g_bnsum[HC];
__device__ float  g_bnsq[HC];

__device__ __forceinline__ float lrelu(float v) { return v > 0.f ? v : NEG_SLOPE * v; }

// ---------------- zero / init ----------------
__global__ void zero_kernel() {
    int t = blockIdx.x * blockDim.x + threadIdx.x;
    if (t < N_NODES) g_deg[t] = 0;
    if (t < HC) { g_bnsum[t] = 0.f; g_bnsq[t] = 0.f; }
    if (t == 0) g_off[N_NODES] = ET;
}

// ---------------- GEMM: h = x @ W  (N x 128) @ (128 x 256) ----------------
// 64-row tiles, K chunked by 32. 256 threads; thread (i = t>>4, j = t&15)
// computes rows i*4..i*4+3, cols j + 16*k (k=0..15).
__global__ void __launch_bounds__(256) gemm_kernel(const float* __restrict__ x,
                                                   const float* __restrict__ W) {
    __shared__ float sAT[32][65];                  // transposed x chunk [k][row]
    __shared__ __align__(16) float sB[32 * 256];   // W chunk, row-major

    const int t = threadIdx.x;
    const int i = t >> 4;      // 0..15 (row group)
    const int j = t & 15;      // 0..15 (col group)
    const int rowBase = blockIdx.x * 64;

    float acc[4][16];
#pragma unroll
    for (int q = 0; q < 4; q++)
#pragma unroll
        for (int k = 0; k < 16; k++) acc[q][k] = 0.f;

    const int cl = t & 31;     // k index for x load
    const int rl = t >> 5;     // 0..7

#pragma unroll 1
    for (int kc = 0; kc < 4; kc++) {
        if (kc) __syncthreads();
        // load x chunk transposed: rows rowBase..rowBase+63, ks kc*32..+31
#pragma unroll
        for (int it = 0; it < 8; it++) {
            int r = rl + 8 * it;
            int grow = rowBase + r;
            float v = 0.f;
            if (grow < N_NODES) v = x[(size_t)grow * IN_C + kc * 32 + cl];
            sAT[cl][r] = v;
        }
        // load W chunk: 32 k-rows x 256 cols = 8192 floats, 32 per thread
#pragma unroll
        for (int it = 0; it < 32; it++) {
            sB[t + 256 * it] = W[kc * 32 * 256 + t + 256 * it];
        }
        __syncthreads();

#pragma unroll 4
        for (int kk = 0; kk < 32; kk++) {
            float a[4];
#pragma unroll
            for (int q = 0; q < 4; q++) a[q] = sAT[kk][i * 4 + q];
            float b[16];
#pragma unroll
            for (int k = 0; k < 16; k++) b[k] = sB[kk * 256 + j + 16 * k];
#pragma unroll
            for (int q = 0; q < 4; q++)
#pragma unroll
                for (int k = 0; k < 16; k++) acc[q][k] = fmaf(a[q], b[k], acc[q][k]);
        }
    }

#pragma unroll
    for (int q = 0; q < 4; q++) {
        int grow = rowBase + i * 4 + q;
        if (grow < N_NODES) {
            float* hp = g_h + (size_t)grow * HC;
#pragma unroll
            for (int k = 0; k < 16; k++) hp[j + 16 * k] = acc[q][k];
        }
    }
}

// ---------------- attention dot products per node (all 4 heads) -------------
// one thread per node; att vectors are tiny and L1/const-cached.
__global__ void attn_dots_kernel(const float* __restrict__ att_src,
                                 const float* __restrict__ att_dst) {
    int n = blockIdx.x * blockDim.x + threadIdx.x;
    if (n >= N_NODES) return;
    const float* hp = g_h + (size_t)n * HC;
    float s[HEADS], d[HEADS];
#pragma unroll
    for (int hd = 0; hd < HEADS; hd++) { s[hd] = 0.f; d[hd] = 0.f; }
#pragma unroll 4
    for (int hd = 0; hd < HEADS; hd++) {
#pragma unroll 8
        for (int c = 0; c < OUT_C; c++) {
            float hv = hp[hd * OUT_C + c];
            s[hd] = fmaf(hv, att_src[hd * OUT_C + c], s[hd]);
            d[hd] = fmaf(hv, att_dst[hd * OUT_C + c], d[hd]);
        }
    }
    g_asrc[n] = make_float4(s[0], s[1], s[2], s[3]);
    g_adst[n] = make_float4(d[0], d[1], d[2], d[3]);
}

// ---------------- CSR build ----------------
__global__ void hist_kernel(const int* __restrict__ ei) {
    int t = blockIdx.x * blockDim.x + threadIdx.x;
    if (t >= ET) return;
    int dst = (t < NE) ? ei[NE + t] : (t - NE);
    if ((unsigned)dst < N_NODES) atomicAdd(&g_deg[dst], 1);
}

__global__ void __launch_bounds__(1024) scan1_kernel() {
    __shared__ int s[1024];
    int t = threadIdx.x;
    int gi = blockIdx.x * 1024 + t;
    int d = (gi < N_NODES) ? g_deg[gi] : 0;
    int v = d;
    s[t] = v;
    __syncthreads();
#pragma unroll
    for (int o = 1; o < 1024; o <<= 1) {
        int add = (t >= o) ? s[t - o] : 0;
        __syncthreads();
        v += add;
        s[t] = v;
        __syncthreads();
    }
    if (gi < N_NODES) g_off[gi] = v - d;   // exclusive within chunk
    if (t == 1023) g_bsum[blockIdx.x] = v; // chunk total
}

__global__ void scan2_kernel() {
    __shared__ int s[128];
    const int NB = (N_NODES + 1023) / 1024;
    int t = threadIdx.x;
    int d = (t < NB) ? g_bsum[t] : 0;
    int v = d;
    s[t] = v;
    __syncthreads();
#pragma unroll
    for (int o = 1; o < 128; o <<= 1) {
        int add = (t >= o) ? s[t - o] : 0;
        __syncthreads();
        v += add;
        s[t] = v;
        __syncthreads();
    }
    if (t < NB) g_bbase[t] = v - d;   // exclusive base per chunk
}

__global__ void __launch_bounds__(1024) scan3_kernel() {
    int t = threadIdx.x;
    int gi = blockIdx.x * 1024 + t;
    if (gi < N_NODES) {
        int o = g_off[gi] + g_bbase[blockIdx.x];
        g_off[gi] = o;
        g_cur[gi] = o;
    }
}

__global__ void fill_kernel(const int* __restrict__ ei) {
    int t = blockIdx.x * blockDim.x + threadIdx.x;
    if (t >= ET) return;
    int src, dst;
    if (t < NE) { src = ei[t]; dst = ei[NE + t]; }
    else        { src = t - NE; dst = t - NE; }
    if ((unsigned)dst >= N_NODES || (unsigned)src >= N_NODES) return;
    int p = atomicAdd(&g_cur[dst], 1);
    g_srcid[p] = src;
}

// ---------------- aggregation: one warp per dst node ----------------
__global__ void __launch_bounds__(256) agg_kernel(const float* __restrict__ bias,
                                                  float* __restrict__ out) {
    const int lane = threadIdx.x & 31;
    const int wpb = blockDim.x >> 5;
    const int wib = threadIdx.x >> 5;                // warp in block
    const int warp = blockIdx.x * wpb + wib;
    const int nwarps = gridDim.x * wpb;

    float bnsum[8], bnsq[8], biasv[8];
#pragma unroll
    for (int i = 0; i < 8; i++) {
        bnsum[i] = 0.f; bnsq[i] = 0.f;
        biasv[i] = bias[lane + 32 * i];
    }

    for (int node = warp; node < N_NODES; node += nwarps) {
        const int beg = g_off[node];
        const int end = g_off[node + 1];
        const float4 ad = g_adst[node];

        // ---- phase A: segment max per head ----
        float m0 = -1e30f, m1 = -1e30f, m2 = -1e30f, m3 = -1e30f;
        for (int e = beg + lane; e < end; e += 32) {
            int s = g_srcid[e];
            float4 as = g_asrc[s];
            m0 = fmaxf(m0, lrelu(as.x + ad.x));
            m1 = fmaxf(m1, lrelu(as.y + ad.y));
            m2 = fmaxf(m2, lrelu(as.z + ad.z));
            m3 = fmaxf(m3, lrelu(as.w + ad.w));
        }
#pragma unroll
        for (int o = 16; o; o >>= 1) {
            m0 = fmaxf(m0, __shfl_xor_sync(0xffffffffu, m0, o));
            m1 = fmaxf(m1, __shfl_xor_sync(0xffffffffu, m1, o));
            m2 = fmaxf(m2, __shfl_xor_sync(0xffffffffu, m2, o));
            m3 = fmaxf(m3, __shfl_xor_sync(0xffffffffu, m3, o));
        }

        // ---- phase B: sum of exp ----
        float s0 = 0.f, s1 = 0.f, s2 = 0.f, s3 = 0.f;
        for (int e = beg + lane; e < end; e += 32) {
            int s = g_srcid[e];
            float4 as = g_asrc[s];
            s0 += __expf(lrelu(as.x + ad.x) - m0);
            s1 += __expf(lrelu(as.y + ad.y) - m1);
            s2 += __expf(lrelu(as.z + ad.z) - m2);
            s3 += __expf(lrelu(as.w + ad.w) - m3);
        }
#pragma unroll
        for (int o = 16; o; o >>= 1) {
            s0 += __shfl_xor_sync(0xffffffffu, s0, o);
            s1 += __shfl_xor_sync(0xffffffffu, s1, o);
            s2 += __shfl_xor_sync(0xffffffffu, s2, o);
            s3 += __shfl_xor_sync(0xffffffffu, s3, o);
        }
        const float i0 = 1.f / (s0 + 1e-16f);
        const float i1 = 1.f / (s1 + 1e-16f);
        const float i2 = 1.f / (s2 + 1e-16f);
        const float i3 = 1.f / (s3 + 1e-16f);

        // ---- phase C: weighted gather-accumulate (warp-uniform edge) ----
        float acc[8];
#pragma unroll
        for (int i = 0; i < 8; i++) acc[i] = 0.f;

        for (int e = beg; e < end; e++) {
            int s = g_srcid[e];                  // broadcast load
            float4 as = g_asrc[s];               // broadcast
            float a0 = __expf(lrelu(as.x + ad.x) - m0) * i0;
            float a1 = __expf(lrelu(as.y + ad.y) - m1) * i1;
            float a2 = __expf(lrelu(as.z + ad.z) - m2) * i2;
            float a3 = __expf(lrelu(as.w + ad.w) - m3) * i3;
            const float* hp = g_h + (size_t)s * HC;
            float h0 = hp[lane +   0], h1 = hp[lane +  32];
            float h2 = hp[lane +  64], h3 = hp[lane +  96];
            float h4 = hp[lane + 128], h5 = hp[lane + 160];
            float h6 = hp[lane + 192], h7 = hp[lane + 224];
            acc[0] = fmaf(h0, a0, acc[0]);
            acc[1] = fmaf(h1, a0, acc[1]);
            acc[2] = fmaf(h2, a1, acc[2]);
            acc[3] = fmaf(h3, a1, acc[3]);
            acc[4] = fmaf(h4, a2, acc[4]);
            acc[5] = fmaf(h5, a2, acc[5]);
            acc[6] = fmaf(h6, a3, acc[6]);
            acc[7] = fmaf(h7, a3, acc[7]);
        }

        float* op = out + (size_t)node * HC;
#pragma unroll
        for (int i = 0; i < 8; i++) {
            float v = acc[i] + biasv[i];
            op[lane + 32 * i] = v;
            bnsum[i] += v;
            bnsq[i] = fmaf(v, v, bnsq[i]);
        }
    }

    // ---- block-level BN partial reduction (no shared atomics) ----
    // each warp owns a private [HC] slice; then tree-combine over 8 warps.
    __shared__ float s_sum[8][HC];
    __shared__ float s_sq[8][HC];
#pragma unroll
    for (int i = 0; i < 8; i++) {
        s_sum[wib][lane + 32 * i] = bnsum[i];
        s_sq[wib][lane + 32 * i] = bnsq[i];
    }
    __syncthreads();
    // 256 threads, each reduces one channel across the 8 warps
    {
        int c = threadIdx.x;
        float ts = 0.f, tq = 0.f;
#pragma unroll
        for (int w = 0; w < 8; w++) { ts += s_sum[w][c]; tq += s_sq[w][c]; }
        atomicAdd(&g_bnsum[c], ts);
        atomicAdd(&g_bnsq[c], tq);
    }
}

// ---------------- BatchNorm + ELU epilogue ----------------
__global__ void bn_elu_kernel(const float* __restrict__ gamma,
                              const float* __restrict__ beta,
                              float* __restrict__ out) {
    size_t idx = (size_t)blockIdx.x * blockDim.x + threadIdx.x;
    if (idx >= (size_t)N_NODES * HC) return;
    int c = (int)(idx & (HC - 1));
    const float invN = 1.f / (float)N_NODES;
    float mean = g_bnsum[c] * invN;
    float var = g_bnsq[c] * invN - mean * mean;
    float v = out[idx];
    float y = gamma[c] * (v - mean) * rsqrtf(var + BN_EPS) + beta[c];
    out[idx] = y > 0.f ? y : expm1f(y);
}

// ---------------- launch ----------------
extern "C" void kernel_launch(void* const* d_in, const int* in_sizes, int n_in,
                              void* d_out, int out_size) {
    const float* x       = (const float*)d_in[0];
    const int*   ei      = (const int*)d_in[1];     // JAX x64 disabled => int32
    const float* W       = (const float*)d_in[2];
    const float* att_src = (const float*)d_in[3];
    const float* att_dst = (const float*)d_in[4];
    const float* bias    = (const float*)d_in[5];
    const float* gamma   = (const float*)d_in[6];
    const float* beta    = (const float*)d_in[7];
    float* out = (float*)d_out;

    zero_kernel<<<(N_NODES + 255) / 256, 256>>>();
    gemm_kernel<<<(N_NODES + 63) / 64, 256>>>(x, W);
    attn_dots_kernel<<<(N_NODES + 255) / 256, 256>>>(att_src, att_dst);
    hist_kernel<<<(ET + 255) / 256, 256>>>(ei);
    scan1_kernel<<<(N_NODES + 1023) / 1024, 1024>>>();
    scan2_kernel<<<1, 128>>>();
    scan3_kernel<<<(N_NODES + 1023) / 1024, 1024>>>();
    fill_kernel<<<(ET + 255) / 256, 256>>>(ei);
    agg_kernel<<<2048, 256>>>(bias, out);
    bn_elu_kernel<<<((size_t)N_NODES * HC + 255) / 256, 256>>>(gamma, beta, out);
}

// round 7
// speedup vs baseline: 1.7043x; 1.7043x over previous
#include <cuda_runtime.h>
#include <cuda_bf16.h>
#include <math.h>

#define N_NODES 100000
#define IN_C    128
#define HEADS   4
#define OUT_C   64
#define HC      256           // HEADS*OUT_C
#define NE      1600000
#define ET      (NE + N_NODES)   // edges + self loops = 1,700,000
#define NEG_SLOPE 0.2f
#define BN_EPS  1e-5f

// ---------------- scratch (device globals; no allocations allowed) ----------
__device__ float  g_h[(size_t)N_NODES * HC];     // projected features, 102.4 MB
__device__ float4 g_asrc[N_NODES];               // per-node src-attn dots (4 heads)
__device__ float4 g_adst[N_NODES];               // per-node dst-attn dots (4 heads)
__device__ int    g_deg[N_NODES];
__device__ int    g_off[N_NODES + 1];
__device__ int    g_cur[N_NODES];
__device__ int    g_srcid[ET];
__device__ int    g_bsum[128];
__device__ int    g_bbase[128];
__device__ float  g_bnsum[HC];
__device__ float  g_bnsq[HC];

__device__ __forceinline__ float lrelu(float v) { return v > 0.f ? v : NEG_SLOPE * v; }

__device__ __forceinline__ unsigned long long pack2(float lo, float hi) {
    unsigned long long r;
    asm("mov.b64 %0, {%1, %2};" : "=l"(r) : "f"(lo), "f"(hi));
    return r;
}
__device__ __forceinline__ void fma2(unsigned long long& acc, unsigned long long a,
                                     unsigned long long b) {
    asm("fma.rn.f32x2 %0, %1, %2, %0;" : "+l"(acc) : "l"(a), "l"(b));
}
__device__ __forceinline__ float selh(float4 v, int h) {
    float t01 = (h & 1) ? v.y : v.x;
    float t23 = (h & 1) ? v.w : v.z;
    return (h & 2) ? t23 : t01;
}

// ---------------- zero / init ----------------
__global__ void zero_kernel() {
    int t = blockIdx.x * blockDim.x + threadIdx.x;
    if (t < N_NODES) g_deg[t] = 0;
    if (t < HC) { g_bnsum[t] = 0.f; g_bnsq[t] = 0.f; }
    if (t == 0) g_off[N_NODES] = ET;
}

// ---------------- GEMM: h = x @ W  (N x 128) @ (128 x 256) ----------------
// 64-row tiles, K chunked by 32. 256 threads; thread (i = t>>4, j = t&15)
// computes rows i*4..i*4+3 and column PAIRS (2j+32k, 2j+32k+1), k=0..7.
// Packed fp32 FMA (fma.rn.f32x2 -> FFMA2) with LDS.64 B operands.
__global__ void __launch_bounds__(256) gemm_kernel(const float* __restrict__ x,
                                                   const float* __restrict__ W) {
    __shared__ float sAT[32][65];                  // transposed x chunk [k][row]
    __shared__ __align__(16) float sB[32 * 256];   // W chunk, row-major

    const int t = threadIdx.x;
    const int i = t >> 4;      // 0..15 (row group)
    const int j = t & 15;      // 0..15 (col-pair group)
    const int rowBase = blockIdx.x * 64;

    unsigned long long acc[4][8];
#pragma unroll
    for (int q = 0; q < 4; q++)
#pragma unroll
        for (int k = 0; k < 8; k++) acc[q][k] = 0ull;

    const int cl = t & 31;     // k index for x load
    const int rl = t >> 5;     // 0..7

#pragma unroll 1
    for (int kc = 0; kc < 4; kc++) {
        if (kc) __syncthreads();
        // load x chunk transposed: rows rowBase..rowBase+63, ks kc*32..+31
#pragma unroll
        for (int it = 0; it < 8; it++) {
            int r = rl + 8 * it;
            int grow = rowBase + r;
            float v = 0.f;
            if (grow < N_NODES) v = x[(size_t)grow * IN_C + kc * 32 + cl];
            sAT[cl][r] = v;
        }
        // load W chunk: 32 k-rows x 256 cols = 2048 float4
        {
            const float4* W4 = (const float4*)(W + kc * 32 * 256);
            float4* sB4 = (float4*)sB;
#pragma unroll
            for (int it = 0; it < 8; it++) sB4[t + 256 * it] = W4[t + 256 * it];
        }
        __syncthreads();

#pragma unroll 4
        for (int kk = 0; kk < 32; kk++) {
            unsigned long long ap[4];
#pragma unroll
            for (int q = 0; q < 4; q++) {
                float a = sAT[kk][i * 4 + q];
                ap[q] = pack2(a, a);
            }
            const unsigned long long* b2 =
                (const unsigned long long*)sB + kk * 128 + j;
#pragma unroll
            for (int k = 0; k < 8; k++) {
                unsigned long long bv = b2[16 * k];
                fma2(acc[0][k], ap[0], bv);
                fma2(acc[1][k], ap[1], bv);
                fma2(acc[2][k], ap[2], bv);
                fma2(acc[3][k], ap[3], bv);
            }
        }
    }

#pragma unroll
    for (int q = 0; q < 4; q++) {
        int grow = rowBase + i * 4 + q;
        if (grow < N_NODES) {
            float2* hp2 = (float2*)(g_h + (size_t)grow * HC);
#pragma unroll
            for (int k = 0; k < 8; k++)
                hp2[j + 16 * k] = *(float2*)&acc[q][k];
        }
    }
}

// ---------------- attention dot products: one warp per node ----------------
__global__ void attn_dots_kernel(const float* __restrict__ att_src,
                                 const float* __restrict__ att_dst) {
    int gt = blockIdx.x * blockDim.x + threadIdx.x;
    int node = gt >> 5;
    int lane = gt & 31;
    if (node >= N_NODES) return;
    const float* hp = g_h + (size_t)node * HC;
    float s[4] = {0.f, 0.f, 0.f, 0.f}, d[4] = {0.f, 0.f, 0.f, 0.f};
#pragma unroll
    for (int ii = 0; ii < 8; ii++) {           // col = lane + 32*ii, head = ii>>1
        int c = lane + 32 * ii;
        float v = hp[c];
        s[ii >> 1] = fmaf(v, att_src[c], s[ii >> 1]);
        d[ii >> 1] = fmaf(v, att_dst[c], d[ii >> 1]);
    }
#pragma unroll
    for (int o = 16; o; o >>= 1) {
#pragma unroll
        for (int h = 0; h < 4; h++) {
            s[h] += __shfl_xor_sync(0xffffffffu, s[h], o);
            d[h] += __shfl_xor_sync(0xffffffffu, d[h], o);
        }
    }
    if (lane == 0) {
        g_asrc[node] = make_float4(s[0], s[1], s[2], s[3]);
        g_adst[node] = make_float4(d[0], d[1], d[2], d[3]);
    }
}

// ---------------- CSR build ----------------
__global__ void hist_kernel(const int* __restrict__ ei) {
    int t = blockIdx.x * blockDim.x + threadIdx.x;
    if (t >= ET) return;
    int dst = (t < NE) ? ei[NE + t] : (t - NE);
    if ((unsigned)dst < N_NODES) atomicAdd(&g_deg[dst], 1);
}

__global__ void __launch_bounds__(1024) scan1_kernel() {
    __shared__ int s[1024];
    int t = threadIdx.x;
    int gi = blockIdx.x * 1024 + t;
    int d = (gi < N_NODES) ? g_deg[gi] : 0;
    int v = d;
    s[t] = v;
    __syncthreads();
#pragma unroll
    for (int o = 1; o < 1024; o <<= 1) {
        int add = (t >= o) ? s[t - o] : 0;
        __syncthreads();
        v += add;
        s[t] = v;
        __syncthreads();
    }
    if (gi < N_NODES) g_off[gi] = v - d;
    if (t == 1023) g_bsum[blockIdx.x] = v;
}

__global__ void scan2_kernel() {
    __shared__ int s[128];
    const int NB = (N_NODES + 1023) / 1024;
    int t = threadIdx.x;
    int d = (t < NB) ? g_bsum[t] : 0;
    int v = d;
    s[t] = v;
    __syncthreads();
#pragma unroll
    for (int o = 1; o < 128; o <<= 1) {
        int add = (t >= o) ? s[t - o] : 0;
        __syncthreads();
        v += add;
        s[t] = v;
        __syncthreads();
    }
    if (t < NB) g_bbase[t] = v - d;
}

__global__ void __launch_bounds__(1024) scan3_kernel() {
    int t = threadIdx.x;
    int gi = blockIdx.x * 1024 + t;
    if (gi < N_NODES) {
        int o = g_off[gi] + g_bbase[blockIdx.x];
        g_off[gi] = o;
        g_cur[gi] = o;
    }
}

__global__ void fill_kernel(const int* __restrict__ ei) {
    int t = blockIdx.x * blockDim.x + threadIdx.x;
    if (t >= ET) return;
    int src, dst;
    if (t < NE) { src = ei[t]; dst = ei[NE + t]; }
    else        { src = t - NE; dst = t - NE; }
    if ((unsigned)dst >= N_NODES || (unsigned)src >= N_NODES) return;
    int p = atomicAdd(&g_cur[dst], 1);
    g_srcid[p] = src;
}

// ---------------- SINGLE-PASS aggregation: one warp per dst node -----------
// out[n] = (Sum_e w_e * h[src_e]) / (Sum_e w_e), w_e = exp(lrelu(asrc+adst)).
// Max subtraction is unnecessary (logits bounded, exp <= ~e^5); normalization
// is deferred to the epilogue. One edge pass instead of three.
// Each lane computes exp only for head (lane&3); shfl redistributes.
__global__ void __launch_bounds__(256) agg_kernel(const float* __restrict__ bias,
                                                  float* __restrict__ out) {
    const int lane = threadIdx.x & 31;
    const int wpb = blockDim.x >> 5;
    const int wib = threadIdx.x >> 5;
    const int warp = blockIdx.x * wpb + wib;
    const int nwarps = gridDim.x * wpb;
    const int hsel = lane & 3;

    float bnsum[8], bnsq[8], biasv[8];
#pragma unroll
    for (int i = 0; i < 8; i++) {
        bnsum[i] = 0.f; bnsq[i] = 0.f;
        biasv[i] = bias[lane + 32 * i];
    }

    for (int node = warp; node < N_NODES; node += nwarps) {
        const int beg = g_off[node];
        const int end = g_off[node + 1];
        const float adv = selh(g_adst[node], hsel);

        float wsum = 0.f;                // per-lane == denom of head (lane&3)
        float acc[8];
#pragma unroll
        for (int i = 0; i < 8; i++) acc[i] = 0.f;

        int e = beg;
        for (; e + 1 < end; e += 2) {
            int s0 = g_srcid[e];
            int s1 = g_srcid[e + 1];
            float4 as0 = g_asrc[s0];
            float4 as1 = g_asrc[s1];
            const float* hp0 = g_h + (size_t)s0 * HC;
            const float* hp1 = g_h + (size_t)s1 * HC;
            float w0 = __expf(lrelu(selh(as0, hsel) + adv));
            float w1 = __expf(lrelu(selh(as1, hsel) + adv));
            wsum += w0 + w1;
            float wa[4], wb[4];
#pragma unroll
            for (int h = 0; h < 4; h++) {
                wa[h] = __shfl_sync(0xffffffffu, w0, h);
                wb[h] = __shfl_sync(0xffffffffu, w1, h);
            }
#pragma unroll
            for (int i = 0; i < 8; i++) {
                acc[i] = fmaf(hp0[lane + 32 * i], wa[i >> 1], acc[i]);
                acc[i] = fmaf(hp1[lane + 32 * i], wb[i >> 1], acc[i]);
            }
        }
        if (e < end) {
            int s0 = g_srcid[e];
            float4 as0 = g_asrc[s0];
            const float* hp0 = g_h + (size_t)s0 * HC;
            float w0 = __expf(lrelu(selh(as0, hsel) + adv));
            wsum += w0;
            float wa[4];
#pragma unroll
            for (int h = 0; h < 4; h++) wa[h] = __shfl_sync(0xffffffffu, w0, h);
#pragma unroll
            for (int i = 0; i < 8; i++)
                acc[i] = fmaf(hp0[lane + 32 * i], wa[i >> 1], acc[i]);
        }

        float inv = 1.f / (wsum + 1e-16f);
        float invh[4];
#pragma unroll
        for (int h = 0; h < 4; h++) invh[h] = __shfl_sync(0xffffffffu, inv, h);

        float* op = out + (size_t)node * HC;
#pragma unroll
        for (int i = 0; i < 8; i++) {
            float v = fmaf(acc[i], invh[i >> 1], biasv[i]);
            op[lane + 32 * i] = v;
            bnsum[i] += v;
            bnsq[i] = fmaf(v, v, bnsq[i]);
        }
    }

    // ---- block-level BN partial reduction ----
    __shared__ float s_sum[8][HC];
    __shared__ float s_sq[8][HC];
#pragma unroll
    for (int i = 0; i < 8; i++) {
        s_sum[wib][lane + 32 * i] = bnsum[i];
        s_sq[wib][lane + 32 * i] = bnsq[i];
    }
    __syncthreads();
    {
        int c = threadIdx.x;
        float ts = 0.f, tq = 0.f;
#pragma unroll
        for (int w = 0; w < 8; w++) { ts += s_sum[w][c]; tq += s_sq[w][c]; }
        atomicAdd(&g_bnsum[c], ts);
        atomicAdd(&g_bnsq[c], tq);
    }
}

// ---------------- BatchNorm + ELU epilogue (float4) ----------------
__global__ void bn_elu_kernel(const float* __restrict__ gamma,
                              const float* __restrict__ beta,
                              float* __restrict__ out) {
    int idx = blockIdx.x * blockDim.x + threadIdx.x;     // over N*HC/4
    if (idx >= N_NODES * (HC / 4)) return;
    int c0 = (idx & 63) * 4;
    const float invN = 1.f / (float)N_NODES;
    float4 v = ((const float4*)out)[idx];
    float r[4] = {v.x, v.y, v.z, v.w};
#pragma unroll
    for (int q = 0; q < 4; q++) {
        int c = c0 + q;
        float mean = g_bnsum[c] * invN;
        float var = g_bnsq[c] * invN - mean * mean;
        float y = gamma[c] * (r[q] - mean) * rsqrtf(var + BN_EPS) + beta[c];
        r[q] = y > 0.f ? y : expm1f(y);
    }
    ((float4*)out)[idx] = make_float4(r[0], r[1], r[2], r[3]);
}

// ---------------- launch ----------------
extern "C" void kernel_launch(void* const* d_in, const int* in_sizes, int n_in,
                              void* d_out, int out_size) {
    const float* x       = (const float*)d_in[0];
    const int*   ei      = (const int*)d_in[1];     // JAX x64 disabled => int32
    const float* W       = (const float*)d_in[2];
    const float* att_src = (const float*)d_in[3];
    const float* att_dst = (const float*)d_in[4];
    const float* bias    = (const float*)d_in[5];
    const float* gamma   = (const float*)d_in[6];
    const float* beta    = (const float*)d_in[7];
    float* out = (float*)d_out;

    zero_kernel<<<(N_NODES + 255) / 256, 256>>>();
    gemm_kernel<<<(N_NODES + 63) / 64, 256>>>(x, W);
    attn_dots_kernel<<<(N_NODES * 32 + 255) / 256, 256>>>(att_src, att_dst);
    hist_kernel<<<(ET + 255) / 256, 256>>>(ei);
    scan1_kernel<<<(N_NODES + 1023) / 1024, 1024>>>();
    scan2_kernel<<<1, 128>>>();
    scan3_kernel<<<(N_NODES + 1023) / 1024, 1024>>>();
    fill_kernel<<<(ET + 255) / 256, 256>>>(ei);
    agg_kernel<<<2048, 256>>>(bias, out);
    bn_elu_kernel<<<(N_NODES * (HC / 4) + 255) / 256, 256>>>(gamma, beta, out);
}

// round 8
// speedup vs baseline: 2.0986x; 1.2314x over previous
#include <cuda_runtime.h>
#include <cuda_bf16.h>
#include <math.h>

#define N_NODES 100000
#define IN_C    128
#define HEADS   4
#define OUT_C   64
#define HC      256           // HEADS*OUT_C
#define NE      1600000
#define ET      (NE + N_NODES)   // edges + self loops = 1,700,000
#define NEG_SLOPE 0.2f
#define BN_EPS  1e-5f

// ---------------- scratch (device globals; no allocations allowed) ----------
__device__ float  g_h[(size_t)N_NODES * HC];     // projected features, 102.4 MB
__device__ float4 g_asrc[N_NODES];               // per-node src-attn dots (4 heads)
__device__ float4 g_adst[N_NODES];               // per-node dst-attn dots (4 heads)
__device__ int    g_deg[N_NODES];
__device__ int    g_off[N_NODES + 1];
__device__ int    g_cur[N_NODES];
__device__ int    g_srcid[ET];
__device__ int    g_bsum[128];
__device__ int    g_bbase[128];
__device__ float  g_bnsum[HC];
__device__ float  g_bnsq[HC];

__device__ __forceinline__ float lrelu(float v) { return v > 0.f ? v : NEG_SLOPE * v; }

__device__ __forceinline__ unsigned long long pack2(float lo, float hi) {
    unsigned long long r;
    asm("mov.b64 %0, {%1, %2};" : "=l"(r) : "f"(lo), "f"(hi));
    return r;
}
__device__ __forceinline__ void fma2(unsigned long long& acc, unsigned long long a,
                                     unsigned long long b) {
    asm("fma.rn.f32x2 %0, %1, %2, %0;" : "+l"(acc) : "l"(a), "l"(b));
}
__device__ __forceinline__ float selh(float4 v, int h) {
    float t01 = (h & 1) ? v.y : v.x;
    float t23 = (h & 1) ? v.w : v.z;
    return (h & 2) ? t23 : t01;
}

// ---------------- zero / init ----------------
__global__ void zero_kernel() {
    int t = blockIdx.x * blockDim.x + threadIdx.x;
    if (t < N_NODES) g_deg[t] = 0;
    if (t < HC) { g_bnsum[t] = 0.f; g_bnsq[t] = 0.f; }
    if (t == 0) g_off[N_NODES] = ET;
}

// ---------------- GEMM: h = x @ W  + fused attention dots ------------------
// 64-row tiles, K chunked by 32. 256 threads; thread (i = t>>4, j = t&15)
// computes rows i*4..i*4+3 and column PAIRS (2j+32k, 2j+32k+1), k=0..7.
// Packed fp32 FMA (fma.rn.f32x2 -> FFMA2) with LDS.64 B operands.
// Epilogue also computes a_src/a_dst per (row, head) from the register tile:
// channel 2j+32k belongs to head k>>1; reduce over j via 16-lane xor shfl.
__global__ void __launch_bounds__(256) gemm_kernel(const float* __restrict__ x,
                                                   const float* __restrict__ W,
                                                   const float* __restrict__ att_src,
                                                   const float* __restrict__ att_dst) {
    __shared__ float sAT[32][65];                  // transposed x chunk [k][row]
    __shared__ __align__(16) float sB[32 * 256];   // W chunk, row-major
    __shared__ float s_as[HC], s_ad[HC];

    const int t = threadIdx.x;
    const int i = t >> 4;      // 0..15 (row group)
    const int j = t & 15;      // 0..15 (col-pair group)
    const int rowBase = blockIdx.x * 64;

    s_as[t] = att_src[t];
    s_ad[t] = att_dst[t];

    unsigned long long acc[4][8];
#pragma unroll
    for (int q = 0; q < 4; q++)
#pragma unroll
        for (int k = 0; k < 8; k++) acc[q][k] = 0ull;

    const int cl = t & 31;     // k index for x load
    const int rl = t >> 5;     // 0..7

#pragma unroll 1
    for (int kc = 0; kc < 4; kc++) {
        if (kc) __syncthreads();
        // load x chunk transposed: rows rowBase..rowBase+63, ks kc*32..+31
#pragma unroll
        for (int it = 0; it < 8; it++) {
            int r = rl + 8 * it;
            int grow = rowBase + r;
            float v = 0.f;
            if (grow < N_NODES) v = x[(size_t)grow * IN_C + kc * 32 + cl];
            sAT[cl][r] = v;
        }
        // load W chunk: 32 k-rows x 256 cols = 2048 float4
        {
            const float4* W4 = (const float4*)(W + kc * 32 * 256);
            float4* sB4 = (float4*)sB;
#pragma unroll
            for (int it = 0; it < 8; it++) sB4[t + 256 * it] = W4[t + 256 * it];
        }
        __syncthreads();

#pragma unroll 4
        for (int kk = 0; kk < 32; kk++) {
            unsigned long long ap[4];
#pragma unroll
            for (int q = 0; q < 4; q++) {
                float a = sAT[kk][i * 4 + q];
                ap[q] = pack2(a, a);
            }
            const unsigned long long* b2 =
                (const unsigned long long*)sB + kk * 128 + j;
#pragma unroll
            for (int k = 0; k < 8; k++) {
                unsigned long long bv = b2[16 * k];
                fma2(acc[0][k], ap[0], bv);
                fma2(acc[1][k], ap[1], bv);
                fma2(acc[2][k], ap[2], bv);
                fma2(acc[3][k], ap[3], bv);
            }
        }
    }

    // att slices for this thread's 16 channels (c = 2j+32k, 2j+32k+1)
    float asLo[8], asHi[8], adLo[8], adHi[8];
#pragma unroll
    for (int k = 0; k < 8; k++) {
        asLo[k] = s_as[2 * j + 32 * k];
        asHi[k] = s_as[2 * j + 32 * k + 1];
        adLo[k] = s_ad[2 * j + 32 * k];
        adHi[k] = s_ad[2 * j + 32 * k + 1];
    }

#pragma unroll
    for (int q = 0; q < 4; q++) {
        int grow = rowBase + i * 4 + q;
        // store h row slice
        if (grow < N_NODES) {
            float2* hp2 = (float2*)(g_h + (size_t)grow * HC);
#pragma unroll
            for (int k = 0; k < 8; k++)
                hp2[j + 16 * k] = *(float2*)&acc[q][k];
        }
        // fused dots: per-head partials over this thread's channels
        float sh[4], dh[4];
#pragma unroll
        for (int h = 0; h < 4; h++) {
            float2 v0 = *(float2*)&acc[q][2 * h];
            float2 v1 = *(float2*)&acc[q][2 * h + 1];
            sh[h] = v0.x * asLo[2 * h] + v0.y * asHi[2 * h]
                  + v1.x * asLo[2 * h + 1] + v1.y * asHi[2 * h + 1];
            dh[h] = v0.x * adLo[2 * h] + v0.y * adHi[2 * h]
                  + v1.x * adLo[2 * h + 1] + v1.y * adHi[2 * h + 1];
        }
        // reduce across the 16 j-lanes (xor offsets stay within 16-lane group)
#pragma unroll
        for (int o = 8; o; o >>= 1) {
#pragma unroll
            for (int h = 0; h < 4; h++) {
                sh[h] += __shfl_xor_sync(0xffffffffu, sh[h], o);
                dh[h] += __shfl_xor_sync(0xffffffffu, dh[h], o);
            }
        }
        if (j == 0 && grow < N_NODES) {
            g_asrc[grow] = make_float4(sh[0], sh[1], sh[2], sh[3]);
            g_adst[grow] = make_float4(dh[0], dh[1], dh[2], dh[3]);
        }
    }
}

// ---------------- CSR build ----------------
__global__ void hist_kernel(const int* __restrict__ ei) {
    int t = blockIdx.x * blockDim.x + threadIdx.x;
    if (t >= ET) return;
    int dst = (t < NE) ? ei[NE + t] : (t - NE);
    if ((unsigned)dst < N_NODES) atomicAdd(&g_deg[dst], 1);
}

__global__ void __launch_bounds__(1024) scan1_kernel() {
    __shared__ int s[1024];
    int t = threadIdx.x;
    int gi = blockIdx.x * 1024 + t;
    int d = (gi < N_NODES) ? g_deg[gi] : 0;
    int v = d;
    s[t] = v;
    __syncthreads();
#pragma unroll
    for (int o = 1; o < 1024; o <<= 1) {
        int add = (t >= o) ? s[t - o] : 0;
        __syncthreads();
        v += add;
        s[t] = v;
        __syncthreads();
    }
    if (gi < N_NODES) g_off[gi] = v - d;
    if (t == 1023) g_bsum[blockIdx.x] = v;
}

__global__ void scan2_kernel() {
    __shared__ int s[128];
    const int NB = (N_NODES + 1023) / 1024;
    int t = threadIdx.x;
    int d = (t < NB) ? g_bsum[t] : 0;
    int v = d;
    s[t] = v;
    __syncthreads();
#pragma unroll
    for (int o = 1; o < 128; o <<= 1) {
        int add = (t >= o) ? s[t - o] : 0;
        __syncthreads();
        v += add;
        s[t] = v;
        __syncthreads();
    }
    if (t < NB) g_bbase[t] = v - d;
}

__global__ void __launch_bounds__(1024) scan3_kernel() {
    int t = threadIdx.x;
    int gi = blockIdx.x * 1024 + t;
    if (gi < N_NODES) {
        int o = g_off[gi] + g_bbase[blockIdx.x];
        g_off[gi] = o;
        g_cur[gi] = o;
    }
}

__global__ void fill_kernel(const int* __restrict__ ei) {
    int t = blockIdx.x * blockDim.x + threadIdx.x;
    if (t >= ET) return;
    int src, dst;
    if (t < NE) { src = ei[t]; dst = ei[NE + t]; }
    else        { src = t - NE; dst = t - NE; }
    if ((unsigned)dst >= N_NODES || (unsigned)src >= N_NODES) return;
    int p = atomicAdd(&g_cur[dst], 1);
    g_srcid[p] = src;
}

// ---------------- SINGLE-PASS aggregation: one warp per dst node -----------
// out[n] = (Sum_e w_e * h[src_e]) / (Sum_e w_e), w_e = exp(lrelu(asrc+adst)).
// Vectorized gather: each lane reads float4 at hp4[lane] (head lane>>4) and
// hp4[lane+32] (head 2|(lane>>4)) -> 2 LDG.128 per edge instead of 8 LDG.32.
__global__ void __launch_bounds__(256) agg_kernel(const float* __restrict__ bias,
                                                  float* __restrict__ out) {
    const int lane = threadIdx.x & 31;
    const int wpb = blockDim.x >> 5;
    const int wib = threadIdx.x >> 5;
    const int warp = blockIdx.x * wpb + wib;
    const int nwarps = gridDim.x * wpb;
    const int hsel = lane & 3;
    const int hA = lane >> 4;        // head of first float4
    const int hB = 2 | (lane >> 4);  // head of second float4

    float4 bnsumA = make_float4(0, 0, 0, 0), bnsumB = make_float4(0, 0, 0, 0);
    float4 bnsqA = make_float4(0, 0, 0, 0), bnsqB = make_float4(0, 0, 0, 0);
    const float4 biasA = ((const float4*)bias)[lane];
    const float4 biasB = ((const float4*)bias)[lane + 32];

    for (int node = warp; node < N_NODES; node += nwarps) {
        const int beg = g_off[node];
        const int end = g_off[node + 1];
        const float adv = selh(g_adst[node], hsel);

        float wsum = 0.f;                 // per-lane == denom of head (lane&3)
        float4 accA = make_float4(0, 0, 0, 0);
        float4 accB = make_float4(0, 0, 0, 0);

        int e = beg;
        for (; e + 1 < end; e += 2) {
            int s0 = g_srcid[e];
            int s1 = g_srcid[e + 1];
            float4 as0 = g_asrc[s0];
            float4 as1 = g_asrc[s1];
            const float4* hp0 = (const float4*)(g_h + (size_t)s0 * HC);
            const float4* hp1 = (const float4*)(g_h + (size_t)s1 * HC);
            float4 h0A = hp0[lane], h0B = hp0[lane + 32];
            float4 h1A = hp1[lane], h1B = hp1[lane + 32];
            float w0 = __expf(lrelu(selh(as0, hsel) + adv));
            float w1 = __expf(lrelu(selh(as1, hsel) + adv));
            wsum += w0 + w1;
            float w0A = __shfl_sync(0xffffffffu, w0, hA);
            float w0B = __shfl_sync(0xffffffffu, w0, hB);
            float w1A = __shfl_sync(0xffffffffu, w1, hA);
            float w1B = __shfl_sync(0xffffffffu, w1, hB);
            accA.x = fmaf(h0A.x, w0A, accA.x); accA.y = fmaf(h0A.y, w0A, accA.y);
            accA.z = fmaf(h0A.z, w0A, accA.z); accA.w = fmaf(h0A.w, w0A, accA.w);
            accB.x = fmaf(h0B.x, w0B, accB.x); accB.y = fmaf(h0B.y, w0B, accB.y);
            accB.z = fmaf(h0B.z, w0B, accB.z); accB.w = fmaf(h0B.w, w0B, accB.w);
            accA.x = fmaf(h1A.x, w1A, accA.x); accA.y = fmaf(h1A.y, w1A, accA.y);
            accA.z = fmaf(h1A.z, w1A, accA.z); accA.w = fmaf(h1A.w, w1A, accA.w);
            accB.x = fmaf(h1B.x, w1B, accB.x); accB.y = fmaf(h1B.y, w1B, accB.y);
            accB.z = fmaf(h1B.z, w1B, accB.z); accB.w = fmaf(h1B.w, w1B, accB.w);
        }
        if (e < end) {
            int s0 = g_srcid[e];
            float4 as0 = g_asrc[s0];
            const float4* hp0 = (const float4*)(g_h + (size_t)s0 * HC);
            float4 h0A = hp0[lane], h0B = hp0[lane + 32];
            float w0 = __expf(lrelu(selh(as0, hsel) + adv));
            wsum += w0;
            float w0A = __shfl_sync(0xffffffffu, w0, hA);
            float w0B = __shfl_sync(0xffffffffu, w0, hB);
            accA.x = fmaf(h0A.x, w0A, accA.x); accA.y = fmaf(h0A.y, w0A, accA.y);
            accA.z = fmaf(h0A.z, w0A, accA.z); accA.w = fmaf(h0A.w, w0A, accA.w);
            accB.x = fmaf(h0B.x, w0B, accB.x); accB.y = fmaf(h0B.y, w0B, accB.y);
            accB.z = fmaf(h0B.z, w0B, accB.z); accB.w = fmaf(h0B.w, w0B, accB.w);
        }

        float inv = 1.f / (wsum + 1e-16f);
        float invA = __shfl_sync(0xffffffffu, inv, hA);
        float invB = __shfl_sync(0xffffffffu, inv, hB);

        float4 vA, vB;
        vA.x = fmaf(accA.x, invA, biasA.x); vA.y = fmaf(accA.y, invA, biasA.y);
        vA.z = fmaf(accA.z, invA, biasA.z); vA.w = fmaf(accA.w, invA, biasA.w);
        vB.x = fmaf(accB.x, invB, biasB.x); vB.y = fmaf(accB.y, invB, biasB.y);
        vB.z = fmaf(accB.z, invB, biasB.z); vB.w = fmaf(accB.w, invB, biasB.w);

        float4* op4 = (float4*)(out + (size_t)node * HC);
        op4[lane] = vA;
        op4[lane + 32] = vB;

        bnsumA.x += vA.x; bnsumA.y += vA.y; bnsumA.z += vA.z; bnsumA.w += vA.w;
        bnsumB.x += vB.x; bnsumB.y += vB.y; bnsumB.z += vB.z; bnsumB.w += vB.w;
        bnsqA.x = fmaf(vA.x, vA.x, bnsqA.x); bnsqA.y = fmaf(vA.y, vA.y, bnsqA.y);
        bnsqA.z = fmaf(vA.z, vA.z, bnsqA.z); bnsqA.w = fmaf(vA.w, vA.w, bnsqA.w);
        bnsqB.x = fmaf(vB.x, vB.x, bnsqB.x); bnsqB.y = fmaf(vB.y, vB.y, bnsqB.y);
        bnsqB.z = fmaf(vB.z, vB.z, bnsqB.z); bnsqB.w = fmaf(vB.w, vB.w, bnsqB.w);
    }

    // ---- block-level BN partial reduction ----
    __shared__ float s_sum[8][HC];
    __shared__ float s_sq[8][HC];
    ((float4*)s_sum[wib])[lane] = bnsumA;
    ((float4*)s_sum[wib])[lane + 32] = bnsumB;
    ((float4*)s_sq[wib])[lane] = bnsqA;
    ((float4*)s_sq[wib])[lane + 32] = bnsqB;
    __syncthreads();
    {
        int c = threadIdx.x;
        float ts = 0.f, tq = 0.f;
#pragma unroll
        for (int w = 0; w < 8; w++) { ts += s_sum[w][c]; tq += s_sq[w][c]; }
        atomicAdd(&g_bnsum[c], ts);
        atomicAdd(&g_bnsq[c], tq);
    }
}

// ---------------- BatchNorm + ELU epilogue (float4) ----------------
__global__ void bn_elu_kernel(const float* __restrict__ gamma,
                              const float* __restrict__ beta,
                              float* __restrict__ out) {
    int idx = blockIdx.x * blockDim.x + threadIdx.x;     // over N*HC/4
    if (idx >= N_NODES * (HC / 4)) return;
    int c0 = (idx & 63) * 4;
    const float invN = 1.f / (float)N_NODES;
    float4 v = ((const float4*)out)[idx];
    float r[4] = {v.x, v.y, v.z, v.w};
#pragma unroll
    for (int q = 0; q < 4; q++) {
        int c = c0 + q;
        float mean = g_bnsum[c] * invN;
        float var = g_bnsq[c] * invN - mean * mean;
        float y = gamma[c] * (r[q] - mean) * rsqrtf(var + BN_EPS) + beta[c];
        r[q] = y > 0.f ? y : expm1f(y);
    }
    ((float4*)out)[idx] = make_float4(r[0], r[1], r[2], r[3]);
}

// ---------------- launch ----------------
extern "C" void kernel_launch(void* const* d_in, const int* in_sizes, int n_in,
                              void* d_out, int out_size) {
    const float* x       = (const float*)d_in[0];
    const int*   ei      = (const int*)d_in[1];     // JAX x64 disabled => int32
    const float* W       = (const float*)d_in[2];
    const float* att_src = (const float*)d_in[3];
    const float* att_dst = (const float*)d_in[4];
    const float* bias    = (const float*)d_in[5];
    const float* gamma   = (const float*)d_in[6];
    const float* beta    = (const float*)d_in[7];
    float* out = (float*)d_out;

    zero_kernel<<<(N_NODES + 255) / 256, 256>>>();
    gemm_kernel<<<(N_NODES + 63) / 64, 256>>>(x, W, att_src, att_dst);
    hist_kernel<<<(ET + 255) / 256, 256>>>(ei);
    scan1_kernel<<<(N_NODES + 1023) / 1024, 1024>>>();
    scan2_kernel<<<1, 128>>>();
    scan3_kernel<<<(N_NODES + 1023) / 1024, 1024>>>();
    fill_kernel<<<(ET + 255) / 256, 256>>>(ei);
    agg_kernel<<<2048, 256>>>(bias, out);
    bn_elu_kernel<<<(N_NODES * (HC / 4) + 255) / 256, 256>>>(gamma, beta, out);
}

// round 9
// speedup vs baseline: 2.5606x; 1.2201x over previous
#include <cuda_runtime.h>
#include <cuda_fp16.h>
#include <math.h>

#define N_NODES 100000
#define IN_C    128
#define HEADS   4
#define OUT_C   64
#define HC      256           // HEADS*OUT_C
#define NE      1600000
#define ET      (NE + N_NODES)   // edges + self loops = 1,700,000
#define NEG_SLOPE 0.2f
#define BN_EPS  1e-5f

// ---------------- scratch (device globals; no allocations allowed) ----------
__device__ __half g_hh[(size_t)N_NODES * HC];    // projected features fp16, 51.2 MB
__device__ float4 g_asrc[N_NODES];               // per-node src-attn dots (4 heads)
__device__ float4 g_adst[N_NODES];               // per-node dst-attn dots (4 heads)
__device__ int    g_deg[N_NODES];
__device__ int    g_off[N_NODES + 1];
__device__ int    g_cur[N_NODES];
__device__ int    g_srcid[ET];
__device__ int    g_bsum[128];
__device__ int    g_bbase[128];
__device__ float  g_bnsum[HC];
__device__ float  g_bnsq[HC];

__device__ __forceinline__ float lrelu(float v) { return v > 0.f ? v : NEG_SLOPE * v; }

__device__ __forceinline__ unsigned long long pack2(float lo, float hi) {
    unsigned long long r;
    asm("mov.b64 %0, {%1, %2};" : "=l"(r) : "f"(lo), "f"(hi));
    return r;
}
__device__ __forceinline__ void fma2(unsigned long long& acc, unsigned long long a,
                                     unsigned long long b) {
    asm("fma.rn.f32x2 %0, %1, %2, %0;" : "+l"(acc) : "l"(a), "l"(b));
}
__device__ __forceinline__ float selh(float4 v, int h) {
    float t01 = (h & 1) ? v.y : v.x;
    float t23 = (h & 1) ? v.w : v.z;
    return (h & 2) ? t23 : t01;
}

// ---------------- zero / init ----------------
__global__ void zero_kernel() {
    int t = blockIdx.x * blockDim.x + threadIdx.x;
    if (t < N_NODES) g_deg[t] = 0;
    if (t < HC) { g_bnsum[t] = 0.f; g_bnsq[t] = 0.f; }
    if (t == 0) g_off[N_NODES] = ET;
}

// ---------------- GEMM: h = x @ W  + fused attention dots ------------------
// 64-row tiles, K chunked by 32. 256 threads; thread (i = t>>4, j = t&15)
// computes rows i*4..i*4+3 and column PAIRS (2j+32k, 2j+32k+1), k=0..7.
// Packed fp32 FMA (fma.rn.f32x2 -> FFMA2) with LDS.64 B operands.
// Epilogue: stores h as fp16 (only consumer is the gather) and computes
// a_src/a_dst per (row, head) from the fp32 register tile (16-lane xor shfl).
__global__ void __launch_bounds__(256) gemm_kernel(const float* __restrict__ x,
                                                   const float* __restrict__ W,
                                                   const float* __restrict__ att_src,
                                                   const float* __restrict__ att_dst) {
    __shared__ float sAT[32][65];                  // transposed x chunk [k][row]
    __shared__ __align__(16) float sB[32 * 256];   // W chunk, row-major
    __shared__ float s_as[HC], s_ad[HC];

    const int t = threadIdx.x;
    const int i = t >> 4;      // 0..15 (row group)
    const int j = t & 15;      // 0..15 (col-pair group)
    const int rowBase = blockIdx.x * 64;

    s_as[t] = att_src[t];
    s_ad[t] = att_dst[t];

    unsigned long long acc[4][8];
#pragma unroll
    for (int q = 0; q < 4; q++)
#pragma unroll
        for (int k = 0; k < 8; k++) acc[q][k] = 0ull;

    const int cl = t & 31;     // k index for x load
    const int rl = t >> 5;     // 0..7

#pragma unroll 1
    for (int kc = 0; kc < 4; kc++) {
        if (kc) __syncthreads();
#pragma unroll
        for (int it = 0; it < 8; it++) {
            int r = rl + 8 * it;
            int grow = rowBase + r;
            float v = 0.f;
            if (grow < N_NODES) v = x[(size_t)grow * IN_C + kc * 32 + cl];
            sAT[cl][r] = v;
        }
        {
            const float4* W4 = (const float4*)(W + kc * 32 * 256);
            float4* sB4 = (float4*)sB;
#pragma unroll
            for (int it = 0; it < 8; it++) sB4[t + 256 * it] = W4[t + 256 * it];
        }
        __syncthreads();

#pragma unroll 4
        for (int kk = 0; kk < 32; kk++) {
            unsigned long long ap[4];
#pragma unroll
            for (int q = 0; q < 4; q++) {
                float a = sAT[kk][i * 4 + q];
                ap[q] = pack2(a, a);
            }
            const unsigned long long* b2 =
                (const unsigned long long*)sB + kk * 128 + j;
#pragma unroll
            for (int k = 0; k < 8; k++) {
                unsigned long long bv = b2[16 * k];
                fma2(acc[0][k], ap[0], bv);
                fma2(acc[1][k], ap[1], bv);
                fma2(acc[2][k], ap[2], bv);
                fma2(acc[3][k], ap[3], bv);
            }
        }
    }

    // att slices for this thread's 16 channels (c = 2j+32k, 2j+32k+1)
    float asLo[8], asHi[8], adLo[8], adHi[8];
#pragma unroll
    for (int k = 0; k < 8; k++) {
        asLo[k] = s_as[2 * j + 32 * k];
        asHi[k] = s_as[2 * j + 32 * k + 1];
        adLo[k] = s_ad[2 * j + 32 * k];
        adHi[k] = s_ad[2 * j + 32 * k + 1];
    }

#pragma unroll
    for (int q = 0; q < 4; q++) {
        int grow = rowBase + i * 4 + q;
        // store h row slice as fp16 (half2 at channel pair 2j+32k)
        if (grow < N_NODES) {
            __half2* hp2 = (__half2*)(g_hh + (size_t)grow * HC);
#pragma unroll
            for (int k = 0; k < 8; k++) {
                float2 v = *(float2*)&acc[q][k];
                hp2[j + 16 * k] = __floats2half2_rn(v.x, v.y);
            }
        }
        // fused dots: per-head partials over this thread's channels
        float sh[4], dh[4];
#pragma unroll
        for (int h = 0; h < 4; h++) {
            float2 v0 = *(float2*)&acc[q][2 * h];
            float2 v1 = *(float2*)&acc[q][2 * h + 1];
            sh[h] = v0.x * asLo[2 * h] + v0.y * asHi[2 * h]
                  + v1.x * asLo[2 * h + 1] + v1.y * asHi[2 * h + 1];
            dh[h] = v0.x * adLo[2 * h] + v0.y * adHi[2 * h]
                  + v1.x * adLo[2 * h + 1] + v1.y * adHi[2 * h + 1];
        }
#pragma unroll
        for (int o = 8; o; o >>= 1) {
#pragma unroll
            for (int h = 0; h < 4; h++) {
                sh[h] += __shfl_xor_sync(0xffffffffu, sh[h], o);
                dh[h] += __shfl_xor_sync(0xffffffffu, dh[h], o);
            }
        }
        if (j == 0 && grow < N_NODES) {
            g_asrc[grow] = make_float4(sh[0], sh[1], sh[2], sh[3]);
            g_adst[grow] = make_float4(dh[0], dh[1], dh[2], dh[3]);
        }
    }
}

// ---------------- CSR build ----------------
__global__ void hist_kernel(const int* __restrict__ ei) {
    int t = blockIdx.x * blockDim.x + threadIdx.x;
    if (t >= ET) return;
    int dst = (t < NE) ? ei[NE + t] : (t - NE);
    if ((unsigned)dst < N_NODES) atomicAdd(&g_deg[dst], 1);
}

__global__ void __launch_bounds__(1024) scan1_kernel() {
    __shared__ int s[1024];
    int t = threadIdx.x;
    int gi = blockIdx.x * 1024 + t;
    int d = (gi < N_NODES) ? g_deg[gi] : 0;
    int v = d;
    s[t] = v;
    __syncthreads();
#pragma unroll
    for (int o = 1; o < 1024; o <<= 1) {
        int add = (t >= o) ? s[t - o] : 0;
        __syncthreads();
        v += add;
        s[t] = v;
        __syncthreads();
    }
    if (gi < N_NODES) g_off[gi] = v - d;
    if (t == 1023) g_bsum[blockIdx.x] = v;
}

__global__ void scan2_kernel() {
    __shared__ int s[128];
    const int NB = (N_NODES + 1023) / 1024;
    int t = threadIdx.x;
    int d = (t < NB) ? g_bsum[t] : 0;
    int v = d;
    s[t] = v;
    __syncthreads();
#pragma unroll
    for (int o = 1; o < 128; o <<= 1) {
        int add = (t >= o) ? s[t - o] : 0;
        __syncthreads();
        v += add;
        s[t] = v;
        __syncthreads();
    }
    if (t < NB) g_bbase[t] = v - d;
}

__global__ void __launch_bounds__(1024) scan3_kernel() {
    int t = threadIdx.x;
    int gi = blockIdx.x * 1024 + t;
    if (gi < N_NODES) {
        int o = g_off[gi] + g_bbase[blockIdx.x];
        g_off[gi] = o;
        g_cur[gi] = o;
    }
}

__global__ void fill_kernel(const int* __restrict__ ei) {
    int t = blockIdx.x * blockDim.x + threadIdx.x;
    if (t >= ET) return;
    int src, dst;
    if (t < NE) { src = ei[t]; dst = ei[NE + t]; }
    else        { src = t - NE; dst = t - NE; }
    if ((unsigned)dst >= N_NODES || (unsigned)src >= N_NODES) return;
    int p = atomicAdd(&g_cur[dst], 1);
    g_srcid[p] = src;
}

// ---------------- SINGLE-PASS aggregation: one warp per dst node -----------
// out[n] = (Sum_e w_e * h[src_e]) / (Sum_e w_e), w_e = exp(lrelu(asrc+adst)).
// fp16 gather: each lane reads ONE uint4 (8 halves = channels lane*8..lane*8+7,
// head = lane>>3) -> 1 LDG.128 per edge per lane, 512B/edge total.
__global__ void __launch_bounds__(256) agg_kernel(const float* __restrict__ bias,
                                                  float* __restrict__ out) {
    const int lane = threadIdx.x & 31;
    const int wpb = blockDim.x >> 5;
    const int wib = threadIdx.x >> 5;
    const int warp = blockIdx.x * wpb + wib;
    const int nwarps = gridDim.x * wpb;
    const int hsel = lane & 3;       // head this lane computes exp for
    const int hmy = lane >> 3;       // head of this lane's 8 channels

    float bnsum[8], bnsq[8], biasv[8];
#pragma unroll
    for (int q = 0; q < 8; q++) {
        bnsum[q] = 0.f; bnsq[q] = 0.f;
        biasv[q] = bias[lane * 8 + q];
    }

    for (int node = warp; node < N_NODES; node += nwarps) {
        const int beg = g_off[node];
        const int end = g_off[node + 1];
        const float adv = selh(g_adst[node], hsel);

        float wsum = 0.f;                 // per-lane == denom of head (lane&3)
        float acc[8];
#pragma unroll
        for (int q = 0; q < 8; q++) acc[q] = 0.f;

        int e = beg;
        for (; e + 1 < end; e += 2) {
            int s0 = g_srcid[e];
            int s1 = g_srcid[e + 1];
            float4 as0 = g_asrc[s0];
            float4 as1 = g_asrc[s1];
            uint4 hv0 = ((const uint4*)(g_hh + (size_t)s0 * HC))[lane];
            uint4 hv1 = ((const uint4*)(g_hh + (size_t)s1 * HC))[lane];
            float w0 = __expf(lrelu(selh(as0, hsel) + adv));
            float w1 = __expf(lrelu(selh(as1, hsel) + adv));
            wsum += w0 + w1;
            float w0m = __shfl_sync(0xffffffffu, w0, hmy);
            float w1m = __shfl_sync(0xffffffffu, w1, hmy);
            {
                float2 f0 = __half22float2(*(__half2*)&hv0.x);
                float2 f1 = __half22float2(*(__half2*)&hv0.y);
                float2 f2 = __half22float2(*(__half2*)&hv0.z);
                float2 f3 = __half22float2(*(__half2*)&hv0.w);
                acc[0] = fmaf(f0.x, w0m, acc[0]); acc[1] = fmaf(f0.y, w0m, acc[1]);
                acc[2] = fmaf(f1.x, w0m, acc[2]); acc[3] = fmaf(f1.y, w0m, acc[3]);
                acc[4] = fmaf(f2.x, w0m, acc[4]); acc[5] = fmaf(f2.y, w0m, acc[5]);
                acc[6] = fmaf(f3.x, w0m, acc[6]); acc[7] = fmaf(f3.y, w0m, acc[7]);
            }
            {
                float2 f0 = __half22float2(*(__half2*)&hv1.x);
                float2 f1 = __half22float2(*(__half2*)&hv1.y);
                float2 f2 = __half22float2(*(__half2*)&hv1.z);
                float2 f3 = __half22float2(*(__half2*)&hv1.w);
                acc[0] = fmaf(f0.x, w1m, acc[0]); acc[1] = fmaf(f0.y, w1m, acc[1]);
                acc[2] = fmaf(f1.x, w1m, acc[2]); acc[3] = fmaf(f1.y, w1m, acc[3]);
                acc[4] = fmaf(f2.x, w1m, acc[4]); acc[5] = fmaf(f2.y, w1m, acc[5]);
                acc[6] = fmaf(f3.x, w1m, acc[6]); acc[7] = fmaf(f3.y, w1m, acc[7]);
            }
        }
        if (e < end) {
            int s0 = g_srcid[e];
            float4 as0 = g_asrc[s0];
            uint4 hv0 = ((const uint4*)(g_hh + (size_t)s0 * HC))[lane];
            float w0 = __expf(lrelu(selh(as0, hsel) + adv));
            wsum += w0;
            float w0m = __shfl_sync(0xffffffffu, w0, hmy);
            float2 f0 = __half22float2(*(__half2*)&hv0.x);
            float2 f1 = __half22float2(*(__half2*)&hv0.y);
            float2 f2 = __half22float2(*(__half2*)&hv0.z);
            float2 f3 = __half22float2(*(__half2*)&hv0.w);
            acc[0] = fmaf(f0.x, w0m, acc[0]); acc[1] = fmaf(f0.y, w0m, acc[1]);
            acc[2] = fmaf(f1.x, w0m, acc[2]); acc[3] = fmaf(f1.y, w0m, acc[3]);
            acc[4] = fmaf(f2.x, w0m, acc[4]); acc[5] = fmaf(f2.y, w0m, acc[5]);
            acc[6] = fmaf(f3.x, w0m, acc[6]); acc[7] = fmaf(f3.y, w0m, acc[7]);
        }

        float inv = 1.f / (wsum + 1e-16f);
        float invm = __shfl_sync(0xffffffffu, inv, hmy);

        float v[8];
#pragma unroll
        for (int q = 0; q < 8; q++) {
            v[q] = fmaf(acc[q], invm, biasv[q]);
            bnsum[q] += v[q];
            bnsq[q] = fmaf(v[q], v[q], bnsq[q]);
        }
        float4* op4 = (float4*)(out + (size_t)node * HC);
        op4[lane * 2]     = make_float4(v[0], v[1], v[2], v[3]);
        op4[lane * 2 + 1] = make_float4(v[4], v[5], v[6], v[7]);
    }

    // ---- block-level BN partial reduction (channel c = lane*8+q) ----
    __shared__ float s_sum[8][HC];
    __shared__ float s_sq[8][HC];
    {
        float4* ss = (float4*)s_sum[wib];
        float4* sq = (float4*)s_sq[wib];
        ss[lane * 2]     = make_float4(bnsum[0], bnsum[1], bnsum[2], bnsum[3]);
        ss[lane * 2 + 1] = make_float4(bnsum[4], bnsum[5], bnsum[6], bnsum[7]);
        sq[lane * 2]     = make_float4(bnsq[0], bnsq[1], bnsq[2], bnsq[3]);
        sq[lane * 2 + 1] = make_float4(bnsq[4], bnsq[5], bnsq[6], bnsq[7]);
    }
    __syncthreads();
    {
        int c = threadIdx.x;
        float ts = 0.f, tq = 0.f;
#pragma unroll
        for (int w = 0; w < 8; w++) { ts += s_sum[w][c]; tq += s_sq[w][c]; }
        atomicAdd(&g_bnsum[c], ts);
        atomicAdd(&g_bnsq[c], tq);
    }
}

// ---------------- BatchNorm + ELU epilogue (float4) ----------------
__global__ void bn_elu_kernel(const float* __restrict__ gamma,
                              const float* __restrict__ beta,
                              float* __restrict__ out) {
    int idx = blockIdx.x * blockDim.x + threadIdx.x;     // over N*HC/4
    if (idx >= N_NODES * (HC / 4)) return;
    int c0 = (idx & 63) * 4;
    const float invN = 1.f / (float)N_NODES;
    float4 v = ((const float4*)out)[idx];
    float r[4] = {v.x, v.y, v.z, v.w};
#pragma unroll
    for (int q = 0; q < 4; q++) {
        int c = c0 + q;
        float mean = g_bnsum[c] * invN;
        float var = g_bnsq[c] * invN - mean * mean;
        float y = gamma[c] * (r[q] - mean) * rsqrtf(var + BN_EPS) + beta[c];
        r[q] = y > 0.f ? y : expm1f(y);
    }
    ((float4*)out)[idx] = make_float4(r[0], r[1], r[2], r[3]);
}

// ---------------- launch ----------------
extern "C" void kernel_launch(void* const* d_in, const int* in_sizes, int n_in,
                              void* d_out, int out_size) {
    const float* x       = (const float*)d_in[0];
    const int*   ei      = (const int*)d_in[1];     // JAX x64 disabled => int32
    const float* W       = (const float*)d_in[2];
    const float* att_src = (const float*)d_in[3];
    const float* att_dst = (const float*)d_in[4];
    const float* bias    = (const float*)d_in[5];
    const float* gamma   = (const float*)d_in[6];
    const float* beta    = (const float*)d_in[7];
    float* out = (float*)d_out;

    zero_kernel<<<(N_NODES + 255) / 256, 256>>>();
    gemm_kernel<<<(N_NODES + 63) / 64, 256>>>(x, W, att_src, att_dst);
    hist_kernel<<<(ET + 255) / 256, 256>>>(ei);
    scan1_kernel<<<(N_NODES + 1023) / 1024, 1024>>>();
    scan2_kernel<<<1, 128>>>();
    scan3_kernel<<<(N_NODES + 1023) / 1024, 1024>>>();
    fill_kernel<<<(ET + 255) / 256, 256>>>(ei);
    agg_kernel<<<2048, 256>>>(bias, out);
    bn_elu_kernel<<<(N_NODES * (HC / 4) + 255) / 256, 256>>>(gamma, beta, out);
}

// round 10
// speedup vs baseline: 2.6836x; 1.0480x over previous
#include <cuda_runtime.h>
#include <cuda_fp16.h>
#include <mma.h>
#include <math.h>

using namespace nvcuda;

#define N_NODES 100000
#define IN_C    128
#define HEADS   4
#define OUT_C   64
#define HC      256           // HEADS*OUT_C
#define NE      1600000
#define ET      (NE + N_NODES)   // edges + self loops = 1,700,000
#define NEG_SLOPE 0.2f
#define BN_EPS  1e-5f

#define LDA 136               // sA row pitch (halves)
#define LDB 272               // sB row pitch (halves)

// ---------------- scratch (device globals; no allocations allowed) ----------
__device__ __align__(16) __half g_hh[(size_t)(N_NODES + 64) * HC]; // fp16 h (+pad tile)
__device__ __align__(16) __half g_Wh[IN_C * HC];   // W in fp16
__device__ float  g_u[2 * 4 * IN_C];               // u[sd][h][k] = (W @ att^T)
__device__ float4 g_asrc[N_NODES];
__device__ float4 g_adst[N_NODES];
__device__ int    g_deg[N_NODES];
__device__ int    g_off[N_NODES + 1];
__device__ int    g_cur[N_NODES];
__device__ int    g_srcid[ET];
__device__ int    g_bsum[128];
__device__ int    g_bbase[128];
__device__ float  g_bnsum[HC];
__device__ float  g_bnsq[HC];

__device__ __forceinline__ float lrelu(float v) { return v > 0.f ? v : NEG_SLOPE * v; }
__device__ __forceinline__ float selh(float4 v, int h) {
    float t01 = (h & 1) ? v.y : v.x;
    float t23 = (h & 1) ? v.w : v.z;
    return (h & 2) ? t23 : t01;
}

// ---------------- zero / init ----------------
__global__ void zero_kernel() {
    int t = blockIdx.x * blockDim.x + threadIdx.x;
    if (t < N_NODES) g_deg[t] = 0;
    if (t < HC) { g_bnsum[t] = 0.f; g_bnsq[t] = 0.f; }
    if (t == 0) g_off[N_NODES] = ET;
}

// ---------------- W -> fp16 ----------------
__global__ void wconv_kernel(const float* __restrict__ W) {
    int idx = blockIdx.x * blockDim.x + threadIdx.x;
    if (idx < IN_C * HC) g_Wh[idx] = __float2half(W[idx]);
}

// ---------------- u[sd][h][k] = sum_c W[k][h*64+c] * att[h][c] ----------------
__global__ void u_kernel(const float* __restrict__ W,
                         const float* __restrict__ att_src,
                         const float* __restrict__ att_dst) {
    int t = threadIdx.x;               // 256 threads
    int sd = t >> 7;
    int k = t & 127;
    const float* att = sd ? att_dst : att_src;
#pragma unroll
    for (int h = 0; h < 4; h++) {
        float s = 0.f;
#pragma unroll 16
        for (int c = 0; c < OUT_C; c++)
            s = fmaf(W[k * HC + h * OUT_C + c], att[h * OUT_C + c], s);
        g_u[sd * 512 + h * 128 + k] = s;
    }
}

// ---------------- GEMM: h = fp16(x @ W) via HMMA (wmma m16n16k16) -----------
// Block: 256 threads (8 warps), tile M=64 N=256 K=128, K chunked by 32.
// Warp w: row tile rt=w&3 (16 rows), col half colBase=(w>>2)*128 (8 col tiles).
__global__ void __launch_bounds__(256) gemm_kernel(const float* __restrict__ x) {
    __shared__ __half sA[64 * LDA];
    __shared__ __half sB[32 * LDB];
    __shared__ float  sC[8][16 * 24];

    const int t = threadIdx.x;
    const int w = t >> 5;
    const int lane = t & 31;
    const int rowBase = blockIdx.x * 64;
    const int rt = w & 3;
    const int colBase = (w >> 2) * 128;

    // load x tile -> fp16 smem (2048 float4, 8 per thread)
#pragma unroll
    for (int i = 0; i < 8; i++) {
        int idx = t + 256 * i;
        int r = idx >> 5, c4 = idx & 31;
        int grow = rowBase + r;
        float4 v = make_float4(0.f, 0.f, 0.f, 0.f);
        if (grow < N_NODES) v = ((const float4*)x)[(size_t)grow * 32 + c4];
        *(__half2*)&sA[r * LDA + c4 * 4]     = __floats2half2_rn(v.x, v.y);
        *(__half2*)&sA[r * LDA + c4 * 4 + 2] = __floats2half2_rn(v.z, v.w);
    }

    wmma::fragment<wmma::accumulator, 16, 16, 16, float> acc[8];
#pragma unroll
    for (int ct = 0; ct < 8; ct++) wmma::fill_fragment(acc[ct], 0.f);

#pragma unroll 1
    for (int kc = 0; kc < 4; kc++) {
        __syncthreads();
        // load W chunk rows kc*32..+31 (1024 uint4, 4 per thread)
#pragma unroll
        for (int i = 0; i < 4; i++) {
            int idx = t + 256 * i;
            int r = idx >> 5, c8 = idx & 31;
            *(uint4*)&sB[r * LDB + c8 * 8] =
                ((const uint4*)(g_Wh + (kc * 32 + r) * HC))[c8];
        }
        __syncthreads();
#pragma unroll
        for (int ks = 0; ks < 2; ks++) {
            wmma::fragment<wmma::matrix_a, 16, 16, 16, __half, wmma::row_major> a;
            wmma::load_matrix_sync(a, &sA[rt * 16 * LDA + kc * 32 + ks * 16], LDA);
#pragma unroll
            for (int ct = 0; ct < 8; ct++) {
                wmma::fragment<wmma::matrix_b, 16, 16, 16, __half, wmma::row_major> b;
                wmma::load_matrix_sync(b, &sB[ks * 16 * LDB + colBase + ct * 16], LDB);
                wmma::mma_sync(acc[ct], a, b, acc[ct]);
            }
        }
    }

    // epilogue: stage each 16x16 fp32 tile in per-warp smem, convert, store fp16
    const int er = lane >> 1;            // 0..15 row in tile
    const int ec = (lane & 1) * 8;       // 0 or 8 col group
#pragma unroll
    for (int ct = 0; ct < 8; ct++) {
        wmma::store_matrix_sync(&sC[w][0], acc[ct], 24, wmma::mem_row_major);
        __syncwarp();
        float4 v0 = *(float4*)&sC[w][er * 24 + ec];
        float4 v1 = *(float4*)&sC[w][er * 24 + ec + 4];
        int grow = rowBase + rt * 16 + er;      // may spill into pad rows (safe)
        uint4 u;
        *(__half2*)&u.x = __floats2half2_rn(v0.x, v0.y);
        *(__half2*)&u.y = __floats2half2_rn(v0.z, v0.w);
        *(__half2*)&u.z = __floats2half2_rn(v1.x, v1.y);
        *(__half2*)&u.w = __floats2half2_rn(v1.z, v1.w);
        *(uint4*)&g_hh[(size_t)grow * HC + colBase + ct * 16 + ec] = u;
        __syncwarp();
    }
}

// ---------------- attention dots from fp32 x: a = x @ u ----------------
// warp per node; lane reads one float4 of x (k = 4*lane..4*lane+3).
__global__ void __launch_bounds__(256) dots_kernel(const float* __restrict__ x) {
    __shared__ float su[1024];           // [sd][h][k]
    int t = threadIdx.x;
#pragma unroll
    for (int i = 0; i < 4; i++) su[t + 256 * i] = g_u[t + 256 * i];
    __syncthreads();

    int node = blockIdx.x * 8 + (t >> 5);
    if (node >= N_NODES) return;
    int lane = t & 31;
    float4 xv = ((const float4*)x)[(size_t)node * 32 + lane];
    int k0 = lane * 4;
    float s[4], d[4];
#pragma unroll
    for (int h = 0; h < 4; h++) {
        float4 us = *(float4*)&su[h * 128 + k0];
        float4 ud = *(float4*)&su[512 + h * 128 + k0];
        s[h] = xv.x * us.x + xv.y * us.y + xv.z * us.z + xv.w * us.w;
        d[h] = xv.x * ud.x + xv.y * ud.y + xv.z * ud.z + xv.w * ud.w;
    }
#pragma unroll
    for (int o = 16; o; o >>= 1) {
#pragma unroll
        for (int h = 0; h < 4; h++) {
            s[h] += __shfl_xor_sync(0xffffffffu, s[h], o);
            d[h] += __shfl_xor_sync(0xffffffffu, d[h], o);
        }
    }
    if (lane == 0) {
        g_asrc[node] = make_float4(s[0], s[1], s[2], s[3]);
        g_adst[node] = make_float4(d[0], d[1], d[2], d[3]);
    }
}

// ---------------- CSR build ----------------
__global__ void hist_kernel(const int* __restrict__ ei) {
    int t = blockIdx.x * blockDim.x + threadIdx.x;
    if (t >= ET) return;
    int dst = (t < NE) ? ei[NE + t] : (t - NE);
    if ((unsigned)dst < N_NODES) atomicAdd(&g_deg[dst], 1);
}

__global__ void __launch_bounds__(1024) scan1_kernel() {
    __shared__ int s[1024];
    int t = threadIdx.x;
    int gi = blockIdx.x * 1024 + t;
    int d = (gi < N_NODES) ? g_deg[gi] : 0;
    int v = d;
    s[t] = v;
    __syncthreads();
#pragma unroll
    for (int o = 1; o < 1024; o <<= 1) {
        int add = (t >= o) ? s[t - o] : 0;
        __syncthreads();
        v += add;
        s[t] = v;
        __syncthreads();
    }
    if (gi < N_NODES) g_off[gi] = v - d;
    if (t == 1023) g_bsum[blockIdx.x] = v;
}

__global__ void scan2_kernel() {
    __shared__ int s[128];
    const int NB = (N_NODES + 1023) / 1024;
    int t = threadIdx.x;
    int d = (t < NB) ? g_bsum[t] : 0;
    int v = d;
    s[t] = v;
    __syncthreads();
#pragma unroll
    for (int o = 1; o < 128; o <<= 1) {
        int add = (t >= o) ? s[t - o] : 0;
        __syncthreads();
        v += add;
        s[t] = v;
        __syncthreads();
    }
    if (t < NB) g_bbase[t] = v - d;
}

__global__ void __launch_bounds__(1024) scan3_kernel() {
    int t = threadIdx.x;
    int gi = blockIdx.x * 1024 + t;
    if (gi < N_NODES) {
        int o = g_off[gi] + g_bbase[blockIdx.x];
        g_off[gi] = o;
        g_cur[gi] = o;
    }
}

__global__ void fill_kernel(const int* __restrict__ ei) {
    int t = blockIdx.x * blockDim.x + threadIdx.x;
    if (t >= ET) return;
    int src, dst;
    if (t < NE) { src = ei[t]; dst = ei[NE + t]; }
    else        { src = t - NE; dst = t - NE; }
    if ((unsigned)dst >= N_NODES || (unsigned)src >= N_NODES) return;
    int p = atomicAdd(&g_cur[dst], 1);
    g_srcid[p] = src;
}

// ---------------- SINGLE-PASS aggregation: one warp per dst node -----------
// out[n] = (Sum_e w_e * h[src_e]) / (Sum_e w_e), w_e = exp(lrelu(asrc+adst)).
// fp16 gather: each lane reads ONE uint4 (8 halves = channels lane*8..lane*8+7,
// head = lane>>3) -> 1 LDG.128 per edge per lane, 512B/edge total.
__global__ void __launch_bounds__(256) agg_kernel(const float* __restrict__ bias,
                                                  float* __restrict__ out) {
    const int lane = threadIdx.x & 31;
    const int wpb = blockDim.x >> 5;
    const int wib = threadIdx.x >> 5;
    const int warp = blockIdx.x * wpb + wib;
    const int nwarps = gridDim.x * wpb;
    const int hsel = lane & 3;       // head this lane computes exp for
    const int hmy = lane >> 3;       // head of this lane's 8 channels

    float bnsum[8], bnsq[8], biasv[8];
#pragma unroll
    for (int q = 0; q < 8; q++) {
        bnsum[q] = 0.f; bnsq[q] = 0.f;
        biasv[q] = bias[lane * 8 + q];
    }

    for (int node = warp; node < N_NODES; node += nwarps) {
        const int beg = g_off[node];
        const int end = g_off[node + 1];
        const float adv = selh(g_adst[node], hsel);

        float wsum = 0.f;
        float acc[8];
#pragma unroll
        for (int q = 0; q < 8; q++) acc[q] = 0.f;

        int e = beg;
        for (; e + 1 < end; e += 2) {
            int s0 = g_srcid[e];
            int s1 = g_srcid[e + 1];
            float4 as0 = g_asrc[s0];
            float4 as1 = g_asrc[s1];
            uint4 hv0 = ((const uint4*)(g_hh + (size_t)s0 * HC))[lane];
            uint4 hv1 = ((const uint4*)(g_hh + (size_t)s1 * HC))[lane];
            float w0 = __expf(lrelu(selh(as0, hsel) + adv));
            float w1 = __expf(lrelu(selh(as1, hsel) + adv));
            wsum += w0 + w1;
            float w0m = __shfl_sync(0xffffffffu, w0, hmy);
            float w1m = __shfl_sync(0xffffffffu, w1, hmy);
            {
                float2 f0 = __half22float2(*(__half2*)&hv0.x);
                float2 f1 = __half22float2(*(__half2*)&hv0.y);
                float2 f2 = __half22float2(*(__half2*)&hv0.z);
                float2 f3 = __half22float2(*(__half2*)&hv0.w);
                acc[0] = fmaf(f0.x, w0m, acc[0]); acc[1] = fmaf(f0.y, w0m, acc[1]);
                acc[2] = fmaf(f1.x, w0m, acc[2]); acc[3] = fmaf(f1.y, w0m, acc[3]);
                acc[4] = fmaf(f2.x, w0m, acc[4]); acc[5] = fmaf(f2.y, w0m, acc[5]);
                acc[6] = fmaf(f3.x, w0m, acc[6]); acc[7] = fmaf(f3.y, w0m, acc[7]);
            }
            {
                float2 f0 = __half22float2(*(__half2*)&hv1.x);
                float2 f1 = __half22float2(*(__half2*)&hv1.y);
                float2 f2 = __half22float2(*(__half2*)&hv1.z);
                float2 f3 = __half22float2(*(__half2*)&hv1.w);
                acc[0] = fmaf(f0.x, w1m, acc[0]); acc[1] = fmaf(f0.y, w1m, acc[1]);
                acc[2] = fmaf(f1.x, w1m, acc[2]); acc[3] = fmaf(f1.y, w1m, acc[3]);
                acc[4] = fmaf(f2.x, w1m, acc[4]); acc[5] = fmaf(f2.y, w1m, acc[5]);
                acc[6] = fmaf(f3.x, w1m, acc[6]); acc[7] = fmaf(f3.y, w1m, acc[7]);
            }
        }
        if (e < end) {
            int s0 = g_srcid[e];
            float4 as0 = g_asrc[s0];
            uint4 hv0 = ((const uint4*)(g_hh + (size_t)s0 * HC))[lane];
            float w0 = __expf(lrelu(selh(as0, hsel) + adv));
            wsum += w0;
            float w0m = __shfl_sync(0xffffffffu, w0, hmy);
            float2 f0 = __half22float2(*(__half2*)&hv0.x);
            float2 f1 = __half22float2(*(__half2*)&hv0.y);
            float2 f2 = __half22float2(*(__half2*)&hv0.z);
            float2 f3 = __half22float2(*(__half2*)&hv0.w);
            acc[0] = fmaf(f0.x, w0m, acc[0]); acc[1] = fmaf(f0.y, w0m, acc[1]);
            acc[2] = fmaf(f1.x, w0m, acc[2]); acc[3] = fmaf(f1.y, w0m, acc[3]);
            acc[4] = fmaf(f2.x, w0m, acc[4]); acc[5] = fmaf(f2.y, w0m, acc[5]);
            acc[6] = fmaf(f3.x, w0m, acc[6]); acc[7] = fmaf(f3.y, w0m, acc[7]);
        }

        float inv = 1.f / (wsum + 1e-16f);
        float invm = __shfl_sync(0xffffffffu, inv, hmy);

        float v[8];
#pragma unroll
        for (int q = 0; q < 8; q++) {
            v[q] = fmaf(acc[q], invm, biasv[q]);
            bnsum[q] += v[q];
            bnsq[q] = fmaf(v[q], v[q], bnsq[q]);
        }
        float4* op4 = (float4*)(out + (size_t)node * HC);
        op4[lane * 2]     = make_float4(v[0], v[1], v[2], v[3]);
        op4[lane * 2 + 1] = make_float4(v[4], v[5], v[6], v[7]);
    }

    // ---- block-level BN partial reduction (channel c = lane*8+q) ----
    __shared__ float s_sum[8][HC];
    __shared__ float s_sq[8][HC];
    {
        float4* ss = (float4*)s_sum[wib];
        float4* sq = (float4*)s_sq[wib];
        ss[lane * 2]     = make_float4(bnsum[0], bnsum[1], bnsum[2], bnsum[3]);
        ss[lane * 2 + 1] = make_float4(bnsum[4], bnsum[5], bnsum[6], bnsum[7]);
        sq[lane * 2]     = make_float4(bnsq[0], bnsq[1], bnsq[2], bnsq[3]);
        sq[lane * 2 + 1] = make_float4(bnsq[4], bnsq[5], bnsq[6], bnsq[7]);
    }
    __syncthreads();
    {
        int c = threadIdx.x;
        float ts = 0.f, tq = 0.f;
#pragma unroll
        for (int w = 0; w < 8; w++) { ts += s_sum[w][c]; tq += s_sq[w][c]; }
        atomicAdd(&g_bnsum[c], ts);
        atomicAdd(&g_bnsq[c], tq);
    }
}

// ---------------- BatchNorm + ELU epilogue (float4) ----------------
__global__ void bn_elu_kernel(const float* __restrict__ gamma,
                              const float* __restrict__ beta,
                              float* __restrict__ out) {
    int idx = blockIdx.x * blockDim.x + threadIdx.x;     // over N*HC/4
    if (idx >= N_NODES * (HC / 4)) return;
    int c0 = (idx & 63) * 4;
    const float invN = 1.f / (float)N_NODES;
    float4 v = ((const float4*)out)[idx];
    float r[4] = {v.x, v.y, v.z, v.w};
#pragma unroll
    for (int q = 0; q < 4; q++) {
        int c = c0 + q;
        float mean = g_bnsum[c] * invN;
        float var = g_bnsq[c] * invN - mean * mean;
        float y = gamma[c] * (r[q] - mean) * rsqrtf(var + BN_EPS) + beta[c];
        r[q] = y > 0.f ? y : expm1f(y);
    }
    ((float4*)out)[idx] = make_float4(r[0], r[1], r[2], r[3]);
}

// ---------------- launch ----------------
extern "C" void kernel_launch(void* const* d_in, const int* in_sizes, int n_in,
                              void* d_out, int out_size) {
    const float* x       = (const float*)d_in[0];
    const int*   ei      = (const int*)d_in[1];     // JAX x64 disabled => int32
    const float* W       = (const float*)d_in[2];
    const float* att_src = (const float*)d_in[3];
    const float* att_dst = (const float*)d_in[4];
    const float* bias    = (const float*)d_in[5];
    const float* gamma   = (const float*)d_in[6];
    const float* beta    = (const float*)d_in[7];
    float* out = (float*)d_out;

    zero_kernel<<<(N_NODES + 255) / 256, 256>>>();
    wconv_kernel<<<(IN_C * HC + 255) / 256, 256>>>(W);
    u_kernel<<<1, 256>>>(W, att_src, att_dst);
    gemm_kernel<<<(N_NODES + 63) / 64, 256>>>(x);
    dots_kernel<<<(N_NODES + 7) / 8, 256>>>(x);
    hist_kernel<<<(ET + 255) / 256, 256>>>(ei);
    scan1_kernel<<<(N_NODES + 1023) / 1024, 1024>>>();
    scan2_kernel<<<1, 128>>>();
    scan3_kernel<<<(N_NODES + 1023) / 1024, 1024>>>();
    fill_kernel<<<(ET + 255) / 256, 256>>>(ei);
    agg_kernel<<<2048, 256>>>(bias, out);
    bn_elu_kernel<<<(N_NODES * (HC / 4) + 255) / 256, 256>>>(gamma, beta, out);
}

// round 12
// speedup vs baseline: 3.1938x; 1.1901x over previous
#include <cuda_runtime.h>
#include <cuda_fp16.h>
#include <mma.h>
#include <math.h>

using namespace nvcuda;

#define N_NODES 100000
#define IN_C    128
#define HEADS   4
#define OUT_C   64
#define HC      256           // HEADS*OUT_C
#define NE      1600000
#define ET      (NE + N_NODES)   // edges + self loops = 1,700,000
#define NEG_SLOPE 0.2f
#define BN_EPS  1e-5f

#define LDA 136               // sA row pitch (halves): 272B -> 4-bank row stride, ok
#define LDB 264               // sB row pitch (halves): 528B -> 33-bank stride, conflict-free

// ---------------- scratch (device globals; no allocations allowed) ----------
__device__ __align__(16) __half g_hh[(size_t)(N_NODES + 64) * HC]; // fp16 h (+pad tile)
__device__ __align__(16) __half g_Wh[IN_C * HC];   // W in fp16
__device__ float  g_u[2 * 4 * IN_C];               // u[sd][h][k] = (W @ att^T)
__device__ float4 g_asrc[N_NODES];
__device__ float4 g_adst[N_NODES];
__device__ int    g_deg[N_NODES];
__device__ int    g_off[N_NODES + 1];
__device__ int    g_cur[N_NODES];
__device__ int    g_srcid[ET];
__device__ int    g_bsum[128];
__device__ int    g_bbase[128];
__device__ float  g_bnsum[HC];
__device__ float  g_bnsq[HC];

__device__ __forceinline__ float lrelu(float v) { return v > 0.f ? v : NEG_SLOPE * v; }
__device__ __forceinline__ float selh(float4 v, int h) {
    float t01 = (h & 1) ? v.y : v.x;
    float t23 = (h & 1) ? v.w : v.z;
    return (h & 2) ? t23 : t01;
}

// ---------------- fused prep: zero + W->fp16 + u = W @ att^T ----------------
__global__ void prep_kernel(const float* __restrict__ W,
                            const float* __restrict__ att_src,
                            const float* __restrict__ att_dst) {
    int t = blockIdx.x * blockDim.x + threadIdx.x;
    if (t < N_NODES) g_deg[t] = 0;
    if (t < HC) { g_bnsum[t] = 0.f; g_bnsq[t] = 0.f; }
    if (t == 0) g_off[N_NODES] = ET;
    if (t < IN_C * HC) g_Wh[t] = __float2half(W[t]);
    if (t < 1024) {                    // u: [sd][h][k]
        int sd = t >> 9, rem = t & 511, h = rem >> 7, k = rem & 127;
        const float* att = sd ? att_dst : att_src;
        float s = 0.f;
#pragma unroll 16
        for (int c = 0; c < OUT_C; c++)
            s = fmaf(W[k * HC + h * OUT_C + c], att[h * OUT_C + c], s);
        g_u[t] = s;
    }
}

// ---------------- GEMM: h = fp16(x @ W) via HMMA (wmma m16n16k16) -----------
// Block: 256 threads (8 warps), tile M=64 N=256 K=128, K chunked by 32.
// Warp grid 2x4: warp w covers rows (w>>2)*32..+31 and cols (w&3)*64..+63.
// Frag loads/block: 8 warps * 8 ksteps * (2 A + 4 B) = 384 (was 576).
__global__ void __launch_bounds__(256) gemm_kernel(const float* __restrict__ x) {
    __shared__ __half sA[64 * LDA];
    __shared__ __half sB[32 * LDB];
    __shared__ float  sC[8][16 * 24];

    const int t = threadIdx.x;
    const int w = t >> 5;
    const int lane = t & 31;
    const int rowBase = blockIdx.x * 64;
    const int rt2 = w >> 2;            // 0..1: 32-row group
    const int cg = w & 3;              // 0..3: 64-col group

    // load x tile -> fp16 smem (2048 float4, 8 per thread)
#pragma unroll
    for (int i = 0; i < 8; i++) {
        int idx = t + 256 * i;
        int r = idx >> 5, c4 = idx & 31;
        int grow = rowBase + r;
        float4 v = make_float4(0.f, 0.f, 0.f, 0.f);
        if (grow < N_NODES) v = ((const float4*)x)[(size_t)grow * 32 + c4];
        *(__half2*)&sA[r * LDA + c4 * 4]     = __floats2half2_rn(v.x, v.y);
        *(__half2*)&sA[r * LDA + c4 * 4 + 2] = __floats2half2_rn(v.z, v.w);
    }

    wmma::fragment<wmma::accumulator, 16, 16, 16, float> acc[2][4];
#pragma unroll
    for (int mi = 0; mi < 2; mi++)
#pragma unroll
        for (int ni = 0; ni < 4; ni++) wmma::fill_fragment(acc[mi][ni], 0.f);

#pragma unroll 1
    for (int kc = 0; kc < 4; kc++) {
        __syncthreads();
        // load W chunk rows kc*32..+31 (1024 uint4, 4 per thread)
#pragma unroll
        for (int i = 0; i < 4; i++) {
            int idx = t + 256 * i;
            int r = idx >> 5, c8 = idx & 31;
            *(uint4*)&sB[r * LDB + c8 * 8] =
                ((const uint4*)(g_Wh + (kc * 32 + r) * HC))[c8];
        }
        __syncthreads();
#pragma unroll
        for (int ks = 0; ks < 2; ks++) {
            wmma::fragment<wmma::matrix_a, 16, 16, 16, __half, wmma::row_major> a[2];
#pragma unroll
            for (int mi = 0; mi < 2; mi++)
                wmma::load_matrix_sync(a[mi],
                    &sA[(rt2 * 32 + mi * 16) * LDA + kc * 32 + ks * 16], LDA);
#pragma unroll
            for (int ni = 0; ni < 4; ni++) {
                wmma::fragment<wmma::matrix_b, 16, 16, 16, __half, wmma::row_major> b;
                wmma::load_matrix_sync(b, &sB[ks * 16 * LDB + cg * 64 + ni * 16], LDB);
#pragma unroll
                for (int mi = 0; mi < 2; mi++)
                    wmma::mma_sync(acc[mi][ni], a[mi], b, acc[mi][ni]);
            }
        }
    }

    // epilogue: stage each 16x16 fp32 tile in per-warp smem, convert, store fp16
    const int er = lane >> 1;            // 0..15 row in tile
    const int ec = (lane & 1) * 8;       // 0 or 8 col group
#pragma unroll
    for (int mi = 0; mi < 2; mi++)
#pragma unroll
    for (int ni = 0; ni < 4; ni++) {
        wmma::store_matrix_sync(&sC[w][0], acc[mi][ni], 24, wmma::mem_row_major);
        __syncwarp();
        float4 v0 = *(float4*)&sC[w][er * 24 + ec];
        float4 v1 = *(float4*)&sC[w][er * 24 + ec + 4];
        int grow = rowBase + rt2 * 32 + mi * 16 + er;  // may hit pad rows (safe)
        uint4 u;
        *(__half2*)&u.x = __floats2half2_rn(v0.x, v0.y);
        *(__half2*)&u.y = __floats2half2_rn(v0.z, v0.w);
        *(__half2*)&u.z = __floats2half2_rn(v1.x, v1.y);
        *(__half2*)&u.w = __floats2half2_rn(v1.z, v1.w);
        *(uint4*)&g_hh[(size_t)grow * HC + cg * 64 + ni * 16 + ec] = u;
        __syncwarp();
    }
}

// ---------------- attention dots from fp32 x: a = x @ u ----------------
__global__ void __launch_bounds__(256) dots_kernel(const float* __restrict__ x) {
    __shared__ float su[1024];           // [sd][h][k]
    int t = threadIdx.x;
#pragma unroll
    for (int i = 0; i < 4; i++) su[t + 256 * i] = g_u[t + 256 * i];
    __syncthreads();

    int node = blockIdx.x * 8 + (t >> 5);
    if (node >= N_NODES) return;
    int lane = t & 31;
    float4 xv = ((const float4*)x)[(size_t)node * 32 + lane];
    int k0 = lane * 4;
    float s[4], d[4];
#pragma unroll
    for (int h = 0; h < 4; h++) {
        float4 us = *(float4*)&su[h * 128 + k0];
        float4 ud = *(float4*)&su[512 + h * 128 + k0];
        s[h] = xv.x * us.x + xv.y * us.y + xv.z * us.z + xv.w * us.w;
        d[h] = xv.x * ud.x + xv.y * ud.y + xv.z * ud.z + xv.w * ud.w;
    }
#pragma unroll
    for (int o = 16; o; o >>= 1) {
#pragma unroll
        for (int h = 0; h < 4; h++) {
            s[h] += __shfl_xor_sync(0xffffffffu, s[h], o);
            d[h] += __shfl_xor_sync(0xffffffffu, d[h], o);
        }
    }
    if (lane == 0) {
        g_asrc[node] = make_float4(s[0], s[1], s[2], s[3]);
        g_adst[node] = make_float4(d[0], d[1], d[2], d[3]);
    }
}

// ---------------- CSR build ----------------
__global__ void hist_kernel(const int* __restrict__ ei) {
    int t = blockIdx.x * blockDim.x + threadIdx.x;
    if (t >= ET) return;
    int dst = (t < NE) ? ei[NE + t] : (t - NE);
    if ((unsigned)dst < N_NODES) atomicAdd(&g_deg[dst], 1);
}

__global__ void __launch_bounds__(1024) scan1_kernel() {
    __shared__ int s[1024];
    int t = threadIdx.x;
    int gi = blockIdx.x * 1024 + t;
    int d = (gi < N_NODES) ? g_deg[gi] : 0;
    int v = d;
    s[t] = v;
    __syncthreads();
#pragma unroll
    for (int o = 1; o < 1024; o <<= 1) {
        int add = (t >= o) ? s[t - o] : 0;
        __syncthreads();
        v += add;
        s[t] = v;
        __syncthreads();
    }
    if (gi < N_NODES) g_off[gi] = v - d;
    if (t == 1023) g_bsum[blockIdx.x] = v;
}

__global__ void scan2_kernel() {
    __shared__ int s[128];
    const int NB = (N_NODES + 1023) / 1024;
    int t = threadIdx.x;
    int d = (t < NB) ? g_bsum[t] : 0;
    int v = d;
    s[t] = v;
    __syncthreads();
#pragma unroll
    for (int o = 1; o < 128; o <<= 1) {
        int add = (t >= o) ? s[t - o] : 0;
        __syncthreads();
        v += add;
        s[t] = v;
        __syncthreads();
    }
    if (t < NB) g_bbase[t] = v - d;
}

__global__ void __launch_bounds__(1024) scan3_kernel() {
    int t = threadIdx.x;
    int gi = blockIdx.x * 1024 + t;
    if (gi < N_NODES) {
        int o = g_off[gi] + g_bbase[blockIdx.x];
        g_off[gi] = o;
        g_cur[gi] = o;
    }
}

__global__ void fill_kernel(const int* __restrict__ ei) {
    int t = blockIdx.x * blockDim.x + threadIdx.x;
    if (t >= ET) return;
    int src, dst;
    if (t < NE) { src = ei[t]; dst = ei[NE + t]; }
    else        { src = t - NE; dst = t - NE; }
    if ((unsigned)dst >= N_NODES || (unsigned)src >= N_NODES) return;
    int p = atomicAdd(&g_cur[dst], 1);
    g_srcid[p] = src;
}

// ---------------- SINGLE-PASS aggregation: one warp per dst node -----------
// Unroll 4 with batched srcid/asrc prefetch for MLP; h loads in 2 pairs.
__device__ __forceinline__ void acc8(float* acc, uint4 hv, float wm) {
    float2 f0 = __half22float2(*(__half2*)&hv.x);
    float2 f1 = __half22float2(*(__half2*)&hv.y);
    float2 f2 = __half22float2(*(__half2*)&hv.z);
    float2 f3 = __half22float2(*(__half2*)&hv.w);
    acc[0] = fmaf(f0.x, wm, acc[0]); acc[1] = fmaf(f0.y, wm, acc[1]);
    acc[2] = fmaf(f1.x, wm, acc[2]); acc[3] = fmaf(f1.y, wm, acc[3]);
    acc[4] = fmaf(f2.x, wm, acc[4]); acc[5] = fmaf(f2.y, wm, acc[5]);
    acc[6] = fmaf(f3.x, wm, acc[6]); acc[7] = fmaf(f3.y, wm, acc[7]);
}

__global__ void __launch_bounds__(256) agg_kernel(const float* __restrict__ bias,
                                                  float* __restrict__ out) {
    const int lane = threadIdx.x & 31;
    const int wpb = blockDim.x >> 5;
    const int wib = threadIdx.x >> 5;
    const int warp = blockIdx.x * wpb + wib;
    const int nwarps = gridDim.x * wpb;
    const int hsel = lane & 3;       // head this lane computes exp for
    const int hmy = lane >> 3;       // head of this lane's 8 channels

    float bnsum[8], bnsq[8], biasv[8];
#pragma unroll
    for (int q = 0; q < 8; q++) {
        bnsum[q] = 0.f; bnsq[q] = 0.f;
        biasv[q] = bias[lane * 8 + q];
    }

    for (int node = warp; node < N_NODES; node += nwarps) {
        const int beg = g_off[node];
        const int end = g_off[node + 1];
        const float adv = selh(g_adst[node], hsel);

        float wsum = 0.f;
        float acc[8];
#pragma unroll
        for (int q = 0; q < 8; q++) acc[q] = 0.f;

        int e = beg;
        for (; e + 3 < end; e += 4) {
            int s0 = g_srcid[e],     s1 = g_srcid[e + 1];
            int s2 = g_srcid[e + 2], s3 = g_srcid[e + 3];
            float4 a0 = g_asrc[s0], a1 = g_asrc[s1];
            float4 a2 = g_asrc[s2], a3 = g_asrc[s3];
            float w0 = __expf(lrelu(selh(a0, hsel) + adv));
            float w1 = __expf(lrelu(selh(a1, hsel) + adv));
            float w2 = __expf(lrelu(selh(a2, hsel) + adv));
            float w3 = __expf(lrelu(selh(a3, hsel) + adv));
            wsum += (w0 + w1) + (w2 + w3);
            float w0m = __shfl_sync(0xffffffffu, w0, hmy);
            float w1m = __shfl_sync(0xffffffffu, w1, hmy);
            float w2m = __shfl_sync(0xffffffffu, w2, hmy);
            float w3m = __shfl_sync(0xffffffffu, w3, hmy);
            {
                uint4 h0 = ((const uint4*)(g_hh + (size_t)s0 * HC))[lane];
                uint4 h1 = ((const uint4*)(g_hh + (size_t)s1 * HC))[lane];
                acc8(acc, h0, w0m);
                acc8(acc, h1, w1m);
            }
            {
                uint4 h2 = ((const uint4*)(g_hh + (size_t)s2 * HC))[lane];
                uint4 h3 = ((const uint4*)(g_hh + (size_t)s3 * HC))[lane];
                acc8(acc, h2, w2m);
                acc8(acc, h3, w3m);
            }
        }
        for (; e < end; e++) {
            int s0 = g_srcid[e];
            float4 a0 = g_asrc[s0];
            uint4 h0 = ((const uint4*)(g_hh + (size_t)s0 * HC))[lane];
            float w0 = __expf(lrelu(selh(a0, hsel) + adv));
            wsum += w0;
            float w0m = __shfl_sync(0xffffffffu, w0, hmy);
            acc8(acc, h0, w0m);
        }

        float inv = 1.f / (wsum + 1e-16f);
        float invm = __shfl_sync(0xffffffffu, inv, hmy);

        float v[8];
#pragma unroll
        for (int q = 0; q < 8; q++) {
            v[q] = fmaf(acc[q], invm, biasv[q]);
            bnsum[q] += v[q];
            bnsq[q] = fmaf(v[q], v[q], bnsq[q]);
        }
        float4* op4 = (float4*)(out + (size_t)node * HC);
        op4[lane * 2]     = make_float4(v[0], v[1], v[2], v[3]);
        op4[lane * 2 + 1] = make_float4(v[4], v[5], v[6], v[7]);
    }

    // ---- block-level BN partial reduction (channel c = lane*8+q) ----
    __shared__ float s_sum[8][HC];
    __shared__ float s_sq[8][HC];
    {
        float4* ss = (float4*)s_sum[wib];
        float4* sq = (float4*)s_sq[wib];
        ss[lane * 2]     = make_float4(bnsum[0], bnsum[1], bnsum[2], bnsum[3]);
        ss[lane * 2 + 1] = make_float4(bnsum[4], bnsum[5], bnsum[6], bnsum[7]);
        sq[lane * 2]     = make_float4(bnsq[0], bnsq[1], bnsq[2], bnsq[3]);
        sq[lane * 2 + 1] = make_float4(bnsq[4], bnsq[5], bnsq[6], bnsq[7]);
    }
    __syncthreads();
    {
        int c = threadIdx.x;
        float ts = 0.f, tq = 0.f;
#pragma unroll
        for (int w = 0; w < 8; w++) { ts += s_sum[w][c]; tq += s_sq[w][c]; }
        atomicAdd(&g_bnsum[c], ts);
        atomicAdd(&g_bnsq[c], tq);
    }
}

// ---------------- BatchNorm + ELU epilogue (float4) ----------------
__global__ void bn_elu_kernel(const float* __restrict__ gamma,
                              const float* __restrict__ beta,
                              float* __restrict__ out) {
    int idx = blockIdx.x * blockDim.x + threadIdx.x;     // over N*HC/4
    if (idx >= N_NODES * (HC / 4)) return;
    int c0 = (idx & 63) * 4;
    const float invN = 1.f / (float)N_NODES;
    float4 v = ((const float4*)out)[idx];
    float r[4] = {v.x, v.y, v.z, v.w};
#pragma unroll
    for (int q = 0; q < 4; q++) {
        int c = c0 + q;
        float mean = g_bnsum[c] * invN;
        float var = g_bnsq[c] * invN - mean * mean;
        float y = gamma[c] * (r[q] - mean) * rsqrtf(var + BN_EPS) + beta[c];
        r[q] = y > 0.f ? y : expm1f(y);
    }
    ((float4*)out)[idx] = make_float4(r[0], r[1], r[2], r[3]);
}

// ---------------- launch ----------------
extern "C" void kernel_launch(void* const* d_in, const int* in_sizes, int n_in,
                              void* d_out, int out_size) {
    const float* x       = (const float*)d_in[0];
    const int*   ei      = (const int*)d_in[1];     // JAX x64 disabled => int32
    const float* W       = (const float*)d_in[2];
    const float* att_src = (const float*)d_in[3];
    const float* att_dst = (const float*)d_in[4];
    const float* bias    = (const float*)d_in[5];
    const float* gamma   = (const float*)d_in[6];
    const float* beta    = (const float*)d_in[7];
    float* out = (float*)d_out;

    prep_kernel<<<(N_NODES + 255) / 256, 256>>>(W, att_src, att_dst);
    gemm_kernel<<<(N_NODES + 63) / 64, 256>>>(x);
    dots_kernel<<<(N_NODES + 7) / 8, 256>>>(x);
    hist_kernel<<<(ET + 255) / 256, 256>>>(ei);
    scan1_kernel<<<(N_NODES + 1023) / 1024, 1024>>>();
    scan2_kernel<<<1, 128>>>();
    scan3_kernel<<<(N_NODES + 1023) / 1024, 1024>>>();
    fill_kernel<<<(ET + 255) / 256, 256>>>(ei);
    agg_kernel<<<2048, 256>>>(bias, out);
    bn_elu_kernel<<<(N_NODES * (HC / 4) + 255) / 256, 256>>>(gamma, beta, out);
}

// round 13
// speedup vs baseline: 3.2157x; 1.0068x over previous
#include <cuda_runtime.h>
#include <cuda_fp16.h>
#include <mma.h>
#include <math.h>

using namespace nvcuda;

#define N_NODES 100000
#define IN_C    128
#define HEADS   4
#define OUT_C   64
#define HC      256           // HEADS*OUT_C
#define NE      1600000
#define ET      (NE + N_NODES)   // edges + self loops = 1,700,000
#define NEG_SLOPE 0.2f
#define BN_EPS  1e-5f

#define LDA 136               // sA row pitch (halves): 272B -> 4-bank row stride, ok
#define LDB 264               // sB row pitch (halves): 528B -> 33-bank stride, conflict-free

// ---------------- scratch (device globals; no allocations allowed) ----------
__device__ __align__(16) __half g_hh[(size_t)(N_NODES + 64) * HC]; // fp16 h (+pad tile)
__device__ __align__(16) __half g_Wh[IN_C * HC];   // W in fp16
__device__ float  g_u[2 * 4 * IN_C];               // u[sd][h][k] = (W @ att^T)
__device__ float4 g_asrc[N_NODES];
__device__ float4 g_adst[N_NODES];
__device__ int    g_deg[N_NODES];
__device__ int    g_off[N_NODES + 1];
__device__ int    g_cur[N_NODES];
__device__ int    g_srcid[ET];
__device__ int    g_bsum[128];
__device__ int    g_bbase[128];
__device__ float  g_bnsum[HC];
__device__ float  g_bnsq[HC];

__device__ __forceinline__ float lrelu(float v) { return v > 0.f ? v : NEG_SLOPE * v; }
__device__ __forceinline__ float selh(float4 v, int h) {
    float t01 = (h & 1) ? v.y : v.x;
    float t23 = (h & 1) ? v.w : v.z;
    return (h & 2) ? t23 : t01;
}

// ---------------- fused prep: zero + W->fp16 + u = W @ att^T ----------------
// g_deg initialized to 1: the self-loop is pre-counted here, so hist only
// processes the NE real edges.
__global__ void prep_kernel(const float* __restrict__ W,
                            const float* __restrict__ att_src,
                            const float* __restrict__ att_dst) {
    int t = blockIdx.x * blockDim.x + threadIdx.x;
    if (t < N_NODES) g_deg[t] = 1;
    if (t < HC) { g_bnsum[t] = 0.f; g_bnsq[t] = 0.f; }
    if (t == 0) g_off[N_NODES] = ET;
    if (t < IN_C * HC) g_Wh[t] = __float2half(W[t]);
    if (t < 1024) {                    // u: [sd][h][k]
        int sd = t >> 9, rem = t & 511, h = rem >> 7, k = rem & 127;
        const float* att = sd ? att_dst : att_src;
        float s = 0.f;
#pragma unroll 16
        for (int c = 0; c < OUT_C; c++)
            s = fmaf(W[k * HC + h * OUT_C + c], att[h * OUT_C + c], s);
        g_u[t] = s;
    }
}

// ---------------- GEMM: h = fp16(x @ W) via HMMA (wmma m16n16k16) -----------
// Block: 256 threads (8 warps), tile M=64 N=256 K=128, K chunked by 32.
// Warp grid 2x4: warp w covers rows (w>>2)*32..+31 and cols (w&3)*64..+63.
__global__ void __launch_bounds__(256) gemm_kernel(const float* __restrict__ x) {
    __shared__ __half sA[64 * LDA];
    __shared__ __half sB[32 * LDB];
    __shared__ float  sC[8][16 * 24];

    const int t = threadIdx.x;
    const int w = t >> 5;
    const int lane = t & 31;
    const int rowBase = blockIdx.x * 64;
    const int rt2 = w >> 2;            // 0..1: 32-row group
    const int cg = w & 3;              // 0..3: 64-col group

    // load x tile -> fp16 smem (2048 float4, 8 per thread)
#pragma unroll
    for (int i = 0; i < 8; i++) {
        int idx = t + 256 * i;
        int r = idx >> 5, c4 = idx & 31;
        int grow = rowBase + r;
        float4 v = make_float4(0.f, 0.f, 0.f, 0.f);
        if (grow < N_NODES) v = ((const float4*)x)[(size_t)grow * 32 + c4];
        *(__half2*)&sA[r * LDA + c4 * 4]     = __floats2half2_rn(v.x, v.y);
        *(__half2*)&sA[r * LDA + c4 * 4 + 2] = __floats2half2_rn(v.z, v.w);
    }

    wmma::fragment<wmma::accumulator, 16, 16, 16, float> acc[2][4];
#pragma unroll
    for (int mi = 0; mi < 2; mi++)
#pragma unroll
        for (int ni = 0; ni < 4; ni++) wmma::fill_fragment(acc[mi][ni], 0.f);

#pragma unroll 1
    for (int kc = 0; kc < 4; kc++) {
        __syncthreads();
        // load W chunk rows kc*32..+31 (1024 uint4, 4 per thread)
#pragma unroll
        for (int i = 0; i < 4; i++) {
            int idx = t + 256 * i;
            int r = idx >> 5, c8 = idx & 31;
            *(uint4*)&sB[r * LDB + c8 * 8] =
                ((const uint4*)(g_Wh + (kc * 32 + r) * HC))[c8];
        }
        __syncthreads();
#pragma unroll
        for (int ks = 0; ks < 2; ks++) {
            wmma::fragment<wmma::matrix_a, 16, 16, 16, __half, wmma::row_major> a[2];
#pragma unroll
            for (int mi = 0; mi < 2; mi++)
                wmma::load_matrix_sync(a[mi],
                    &sA[(rt2 * 32 + mi * 16) * LDA + kc * 32 + ks * 16], LDA);
#pragma unroll
            for (int ni = 0; ni < 4; ni++) {
                wmma::fragment<wmma::matrix_b, 16, 16, 16, __half, wmma::row_major> b;
                wmma::load_matrix_sync(b, &sB[ks * 16 * LDB + cg * 64 + ni * 16], LDB);
#pragma unroll
                for (int mi = 0; mi < 2; mi++)
                    wmma::mma_sync(acc[mi][ni], a[mi], b, acc[mi][ni]);
            }
        }
    }

    // epilogue: stage each 16x16 fp32 tile in per-warp smem, convert, store fp16
    const int er = lane >> 1;            // 0..15 row in tile
    const int ec = (lane & 1) * 8;       // 0 or 8 col group
#pragma unroll
    for (int mi = 0; mi < 2; mi++)
#pragma unroll
    for (int ni = 0; ni < 4; ni++) {
        wmma::store_matrix_sync(&sC[w][0], acc[mi][ni], 24, wmma::mem_row_major);
        __syncwarp();
        float4 v0 = *(float4*)&sC[w][er * 24 + ec];
        float4 v1 = *(float4*)&sC[w][er * 24 + ec + 4];
        int grow = rowBase + rt2 * 32 + mi * 16 + er;  // may hit pad rows (safe)
        uint4 u;
        *(__half2*)&u.x = __floats2half2_rn(v0.x, v0.y);
        *(__half2*)&u.y = __floats2half2_rn(v0.z, v0.w);
        *(__half2*)&u.z = __floats2half2_rn(v1.x, v1.y);
        *(__half2*)&u.w = __floats2half2_rn(v1.z, v1.w);
        *(uint4*)&g_hh[(size_t)grow * HC + cg * 64 + ni * 16 + ec] = u;
        __syncwarp();
    }
}

// ---------------- attention dots from fp32 x: a = x @ u ----------------
__global__ void __launch_bounds__(256) dots_kernel(const float* __restrict__ x) {
    __shared__ float su[1024];           // [sd][h][k]
    int t = threadIdx.x;
#pragma unroll
    for (int i = 0; i < 4; i++) su[t + 256 * i] = g_u[t + 256 * i];
    __syncthreads();

    int node = blockIdx.x * 8 + (t >> 5);
    if (node >= N_NODES) return;
    int lane = t & 31;
    float4 xv = ((const float4*)x)[(size_t)node * 32 + lane];
    int k0 = lane * 4;
    float s[4], d[4];
#pragma unroll
    for (int h = 0; h < 4; h++) {
        float4 us = *(float4*)&su[h * 128 + k0];
        float4 ud = *(float4*)&su[512 + h * 128 + k0];
        s[h] = xv.x * us.x + xv.y * us.y + xv.z * us.z + xv.w * us.w;
        d[h] = xv.x * ud.x + xv.y * ud.y + xv.z * ud.z + xv.w * ud.w;
    }
#pragma unroll
    for (int o = 16; o; o >>= 1) {
#pragma unroll
        for (int h = 0; h < 4; h++) {
            s[h] += __shfl_xor_sync(0xffffffffu, s[h], o);
            d[h] += __shfl_xor_sync(0xffffffffu, d[h], o);
        }
    }
    if (lane == 0) {
        g_asrc[node] = make_float4(s[0], s[1], s[2], s[3]);
        g_adst[node] = make_float4(d[0], d[1], d[2], d[3]);
    }
}

// ---------------- CSR build ----------------
// hist: 4 edges per thread via int4 (self-loops pre-counted in prep).
__global__ void hist_kernel(const int* __restrict__ ei) {
    int t = blockIdx.x * blockDim.x + threadIdx.x;
    if (t >= NE / 4) return;
    int4 d = ((const int4*)(ei + NE))[t];
    if ((unsigned)d.x < N_NODES) atomicAdd(&g_deg[d.x], 1);
    if ((unsigned)d.y < N_NODES) atomicAdd(&g_deg[d.y], 1);
    if ((unsigned)d.z < N_NODES) atomicAdd(&g_deg[d.z], 1);
    if ((unsigned)d.w < N_NODES) atomicAdd(&g_deg[d.w], 1);
}

__global__ void __launch_bounds__(1024) scan1_kernel() {
    __shared__ int s[1024];
    int t = threadIdx.x;
    int gi = blockIdx.x * 1024 + t;
    int d = (gi < N_NODES) ? g_deg[gi] : 0;
    int v = d;
    s[t] = v;
    __syncthreads();
#pragma unroll
    for (int o = 1; o < 1024; o <<= 1) {
        int add = (t >= o) ? s[t - o] : 0;
        __syncthreads();
        v += add;
        s[t] = v;
        __syncthreads();
    }
    if (gi < N_NODES) g_off[gi] = v - d;
    if (t == 1023) g_bsum[blockIdx.x] = v;
}

__global__ void scan2_kernel() {
    __shared__ int s[128];
    const int NB = (N_NODES + 1023) / 1024;
    int t = threadIdx.x;
    int d = (t < NB) ? g_bsum[t] : 0;
    int v = d;
    s[t] = v;
    __syncthreads();
#pragma unroll
    for (int o = 1; o < 128; o <<= 1) {
        int add = (t >= o) ? s[t - o] : 0;
        __syncthreads();
        v += add;
        s[t] = v;
        __syncthreads();
    }
    if (t < NB) g_bbase[t] = v - d;
}

__global__ void __launch_bounds__(1024) scan3_kernel() {
    int t = threadIdx.x;
    int gi = blockIdx.x * 1024 + t;
    if (gi < N_NODES) {
        int o = g_off[gi] + g_bbase[blockIdx.x];
        g_off[gi] = o;
        g_cur[gi] = o;
    }
}

// fill: threads [0, NE/4) handle 4 real edges via int4; threads
// [NE/4, NE/4 + N_NODES) place the self-loops.
__global__ void fill_kernel(const int* __restrict__ ei) {
    int t = blockIdx.x * blockDim.x + threadIdx.x;
    if (t < NE / 4) {
        int4 s4 = ((const int4*)ei)[t];
        int4 d4 = ((const int4*)(ei + NE))[t];
        if ((unsigned)d4.x < N_NODES && (unsigned)s4.x < N_NODES)
            g_srcid[atomicAdd(&g_cur[d4.x], 1)] = s4.x;
        if ((unsigned)d4.y < N_NODES && (unsigned)s4.y < N_NODES)
            g_srcid[atomicAdd(&g_cur[d4.y], 1)] = s4.y;
        if ((unsigned)d4.z < N_NODES && (unsigned)s4.z < N_NODES)
            g_srcid[atomicAdd(&g_cur[d4.z], 1)] = s4.z;
        if ((unsigned)d4.w < N_NODES && (unsigned)s4.w < N_NODES)
            g_srcid[atomicAdd(&g_cur[d4.w], 1)] = s4.w;
    } else {
        int n = t - NE / 4;
        if (n < N_NODES)
            g_srcid[atomicAdd(&g_cur[n], 1)] = n;
    }
}

// ---------------- SINGLE-PASS aggregation: one warp per dst node -----------
// Pipelined: h loads issued immediately from srcid (before exp/shfl chain);
// next batch's srcid prefetched before the FMA block.
__device__ __forceinline__ void acc8(float* acc, uint4 hv, float wm) {
    float2 f0 = __half22float2(*(__half2*)&hv.x);
    float2 f1 = __half22float2(*(__half2*)&hv.y);
    float2 f2 = __half22float2(*(__half2*)&hv.z);
    float2 f3 = __half22float2(*(__half2*)&hv.w);
    acc[0] = fmaf(f0.x, wm, acc[0]); acc[1] = fmaf(f0.y, wm, acc[1]);
    acc[2] = fmaf(f1.x, wm, acc[2]); acc[3] = fmaf(f1.y, wm, acc[3]);
    acc[4] = fmaf(f2.x, wm, acc[4]); acc[5] = fmaf(f2.y, wm, acc[5]);
    acc[6] = fmaf(f3.x, wm, acc[6]); acc[7] = fmaf(f3.y, wm, acc[7]);
}

__global__ void __launch_bounds__(256) agg_kernel(const float* __restrict__ bias,
                                                  float* __restrict__ out) {
    const int lane = threadIdx.x & 31;
    const int wpb = blockDim.x >> 5;
    const int wib = threadIdx.x >> 5;
    const int warp = blockIdx.x * wpb + wib;
    const int nwarps = gridDim.x * wpb;
    const int hsel = lane & 3;       // head this lane computes exp for
    const int hmy = lane >> 3;       // head of this lane's 8 channels

    float bnsum[8], bnsq[8], biasv[8];
#pragma unroll
    for (int q = 0; q < 8; q++) {
        bnsum[q] = 0.f; bnsq[q] = 0.f;
        biasv[q] = bias[lane * 8 + q];
    }

    for (int node = warp; node < N_NODES; node += nwarps) {
        const int beg = g_off[node];
        const int end = g_off[node + 1];
        const float adv = selh(g_adst[node], hsel);

        float wsum = 0.f;
        float acc[8];
#pragma unroll
        for (int q = 0; q < 8; q++) acc[q] = 0.f;

        const int n4 = (end - beg) >> 2;   // full 4-edge groups
        int e = beg;
        int s0, s1, s2, s3;
        if (n4 > 0) {
            s0 = g_srcid[e]; s1 = g_srcid[e + 1];
            s2 = g_srcid[e + 2]; s3 = g_srcid[e + 3];
        }
        for (int g = 0; g < n4; g++) {
            // issue the 4 big gathers first (independent of logits)
            uint4 h0 = ((const uint4*)(g_hh + (size_t)s0 * HC))[lane];
            uint4 h1 = ((const uint4*)(g_hh + (size_t)s1 * HC))[lane];
            uint4 h2 = ((const uint4*)(g_hh + (size_t)s2 * HC))[lane];
            uint4 h3 = ((const uint4*)(g_hh + (size_t)s3 * HC))[lane];
            float4 a0 = g_asrc[s0], a1 = g_asrc[s1];
            float4 a2 = g_asrc[s2], a3 = g_asrc[s3];
            // prefetch next batch of indices
            e += 4;
            int t0 = s0, t1 = s1, t2 = s2, t3 = s3;  (void)t0;(void)t1;(void)t2;(void)t3;
            if (g + 1 < n4) {
                s0 = g_srcid[e]; s1 = g_srcid[e + 1];
                s2 = g_srcid[e + 2]; s3 = g_srcid[e + 3];
            }
            // exp + shfl overlap with in-flight h loads
            float w0 = __expf(lrelu(selh(a0, hsel) + adv));
            float w1 = __expf(lrelu(selh(a1, hsel) + adv));
            float w2 = __expf(lrelu(selh(a2, hsel) + adv));
            float w3 = __expf(lrelu(selh(a3, hsel) + adv));
            wsum += (w0 + w1) + (w2 + w3);
            float w0m = __shfl_sync(0xffffffffu, w0, hmy);
            float w1m = __shfl_sync(0xffffffffu, w1, hmy);
            float w2m = __shfl_sync(0xffffffffu, w2, hmy);
            float w3m = __shfl_sync(0xffffffffu, w3, hmy);
            acc8(acc, h0, w0m);
            acc8(acc, h1, w1m);
            acc8(acc, h2, w2m);
            acc8(acc, h3, w3m);
        }
        for (; e < end; e++) {
            int sv = g_srcid[e];
            float4 a0 = g_asrc[sv];
            uint4 h0 = ((const uint4*)(g_hh + (size_t)sv * HC))[lane];
            float w0 = __expf(lrelu(selh(a0, hsel) + adv));
            wsum += w0;
            float w0m = __shfl_sync(0xffffffffu, w0, hmy);
            acc8(acc, h0, w0m);
        }

        float inv = 1.f / (wsum + 1e-16f);
        float invm = __shfl_sync(0xffffffffu, inv, hmy);

        float v[8];
#pragma unroll
        for (int q = 0; q < 8; q++) {
            v[q] = fmaf(acc[q], invm, biasv[q]);
            bnsum[q] += v[q];
            bnsq[q] = fmaf(v[q], v[q], bnsq[q]);
        }
        float4* op4 = (float4*)(out + (size_t)node * HC);
        op4[lane * 2]     = make_float4(v[0], v[1], v[2], v[3]);
        op4[lane * 2 + 1] = make_float4(v[4], v[5], v[6], v[7]);
    }

    // ---- block-level BN partial reduction (channel c = lane*8+q) ----
    __shared__ float s_sum[8][HC];
    __shared__ float s_sq[8][HC];
    {
        float4* ss = (float4*)s_sum[wib];
        float4* sq = (float4*)s_sq[wib];
        ss[lane * 2]     = make_float4(bnsum[0], bnsum[1], bnsum[2], bnsum[3]);
        ss[lane * 2 + 1] = make_float4(bnsum[4], bnsum[5], bnsum[6], bnsum[7]);
        sq[lane * 2]     = make_float4(bnsq[0], bnsq[1], bnsq[2], bnsq[3]);
        sq[lane * 2 + 1] = make_float4(bnsq[4], bnsq[5], bnsq[6], bnsq[7]);
    }
    __syncthreads();
    {
        int c = threadIdx.x;
        float ts = 0.f, tq = 0.f;
#pragma unroll
        for (int w = 0; w < 8; w++) { ts += s_sum[w][c]; tq += s_sq[w][c]; }
        atomicAdd(&g_bnsum[c], ts);
        atomicAdd(&g_bnsq[c], tq);
    }
}

// ---------------- BatchNorm + ELU epilogue (float4) ----------------
__global__ void bn_elu_kernel(const float* __restrict__ gamma,
                              const float* __restrict__ beta,
                              float* __restrict__ out) {
    int idx = blockIdx.x * blockDim.x + threadIdx.x;     // over N*HC/4
    if (idx >= N_NODES * (HC / 4)) return;
    int c0 = (idx & 63) * 4;
    const float invN = 1.f / (float)N_NODES;
    float4 v = ((const float4*)out)[idx];
    float r[4] = {v.x, v.y, v.z, v.w};
#pragma unroll
    for (int q = 0; q < 4; q++) {
        int c = c0 + q;
        float mean = g_bnsum[c] * invN;
        float var = g_bnsq[c] * invN - mean * mean;
        float y = gamma[c] * (r[q] - mean) * rsqrtf(var + BN_EPS) + beta[c];
        r[q] = y > 0.f ? y : expm1f(y);
    }
    ((float4*)out)[idx] = make_float4(r[0], r[1], r[2], r[3]);
}

// ---------------- launch ----------------
extern "C" void kernel_launch(void* const* d_in, const int* in_sizes, int n_in,
                              void* d_out, int out_size) {
    const float* x       = (const float*)d_in[0];
    const int*   ei      = (const int*)d_in[1];     // JAX x64 disabled => int32
    const float* W       = (const float*)d_in[2];
    const float* att_src = (const float*)d_in[3];
    const float* att_dst = (const float*)d_in[4];
    const float* bias    = (const float*)d_in[5];
    const float* gamma   = (const float*)d_in[6];
    const float* beta    = (const float*)d_in[7];
    float* out = (float*)d_out;

    prep_kernel<<<(N_NODES + 255) / 256, 256>>>(W, att_src, att_dst);
    gemm_kernel<<<(N_NODES + 63) / 64, 256>>>(x);
    dots_kernel<<<(N_NODES + 7) / 8, 256>>>(x);
    hist_kernel<<<(NE / 4 + 255) / 256, 256>>>(ei);
    scan1_kernel<<<(N_NODES + 1023) / 1024, 1024>>>();
    scan2_kernel<<<1, 128>>>();
    scan3_kernel<<<(N_NODES + 1023) / 1024, 1024>>>();
    fill_kernel<<<(NE / 4 + N_NODES + 255) / 256, 256>>>(ei);
    agg_kernel<<<2048, 256>>>(bias, out);
    bn_elu_kernel<<<(N_NODES * (HC / 4) + 255) / 256, 256>>>(gamma, beta, out);
}

// round 15
// speedup vs baseline: 3.2665x; 1.0158x over previous
#include <cuda_runtime.h>
#include <cuda_fp16.h>
#include <mma.h>
#include <math.h>

using namespace nvcuda;

#define N_NODES 100000
#define IN_C    128
#define HEADS   4
#define OUT_C   64
#define HC      256           // HEADS*OUT_C
#define NE      1600000
#define ET      (NE + N_NODES)   // edges + self loops = 1,700,000
#define NEG_SLOPE 0.2f
#define BN_EPS  1e-5f

#define LDA 136               // sA row pitch (halves)
#define LDB 264               // sB row pitch (halves): 528B -> conflict-free LDSM

// ---------------- scratch (device globals; no allocations allowed) ----------
__device__ __align__(16) __half g_hh[(size_t)(N_NODES + 64) * HC]; // fp16 h (+pad tile)
__device__ __align__(16) __half g_Wh[IN_C * HC];   // W in fp16
__device__ float  g_u[2 * 4 * IN_C];               // u[sd][h][k] = (W @ att^T)
__device__ float4 g_asrc[N_NODES];
__device__ float4 g_adst[N_NODES];
__device__ int    g_deg[N_NODES];
__device__ int    g_off[N_NODES + 1];
__device__ unsigned short g_rank[NE];              // per-edge rank within dst list
__device__ int    g_srcid[ET];
__device__ int    g_bsum[128];
__device__ int    g_bbase[128];
__device__ float  g_bnsum[HC];
__device__ float  g_bnsq[HC];

__device__ __forceinline__ float lrelu(float v) { return v > 0.f ? v : NEG_SLOPE * v; }
__device__ __forceinline__ float selh(float4 v, int h) {
    float t01 = (h & 1) ? v.y : v.x;
    float t23 = (h & 1) ? v.w : v.z;
    return (h & 2) ? t23 : t01;
}

// ---------------- fused prep: zero + W->fp16 + u = W @ att^T ----------------
// g_deg initialized to 1: slot 0 of every node's CSR list is its self-loop.
__global__ void prep_kernel(const float* __restrict__ W,
                            const float* __restrict__ att_src,
                            const float* __restrict__ att_dst) {
    int t = blockIdx.x * blockDim.x + threadIdx.x;
    if (t < N_NODES) g_deg[t] = 1;
    if (t < HC) { g_bnsum[t] = 0.f; g_bnsq[t] = 0.f; }
    if (t == 0) g_off[N_NODES] = ET;
    if (t < IN_C * HC) g_Wh[t] = __float2half(W[t]);
    if (t < 1024) {                    // u: [sd][h][k]
        int sd = t >> 9, rem = t & 511, h = rem >> 7, k = rem & 127;
        const float* att = sd ? att_dst : att_src;
        float s = 0.f;
#pragma unroll 16
        for (int c = 0; c < OUT_C; c++)
            s = fmaf(W[k * HC + h * OUT_C + c], att[h * OUT_C + c], s);
        g_u[t] = s;
    }
}

// ---------------- GEMM: h = fp16(x @ W) via HMMA (wmma m16n16k16) -----------
__global__ void __launch_bounds__(256) gemm_kernel(const float* __restrict__ x) {
    __shared__ __half sA[64 * LDA];
    __shared__ __half sB[32 * LDB];
    __shared__ float  sC[8][16 * 24];

    const int t = threadIdx.x;
    const int w = t >> 5;
    const int lane = t & 31;
    const int rowBase = blockIdx.x * 64;
    const int rt2 = w >> 2;            // 0..1: 32-row group
    const int cg = w & 3;              // 0..3: 64-col group

#pragma unroll
    for (int i = 0; i < 8; i++) {
        int idx = t + 256 * i;
        int r = idx >> 5, c4 = idx & 31;
        int grow = rowBase + r;
        float4 v = make_float4(0.f, 0.f, 0.f, 0.f);
        if (grow < N_NODES) v = ((const float4*)x)[(size_t)grow * 32 + c4];
        *(__half2*)&sA[r * LDA + c4 * 4]     = __floats2half2_rn(v.x, v.y);
        *(__half2*)&sA[r * LDA + c4 * 4 + 2] = __floats2half2_rn(v.z, v.w);
    }

    wmma::fragment<wmma::accumulator, 16, 16, 16, float> acc[2][4];
#pragma unroll
    for (int mi = 0; mi < 2; mi++)
#pragma unroll
        for (int ni = 0; ni < 4; ni++) wmma::fill_fragment(acc[mi][ni], 0.f);

#pragma unroll 1
    for (int kc = 0; kc < 4; kc++) {
        __syncthreads();
#pragma unroll
        for (int i = 0; i < 4; i++) {
            int idx = t + 256 * i;
            int r = idx >> 5, c8 = idx & 31;
            *(uint4*)&sB[r * LDB + c8 * 8] =
                ((const uint4*)(g_Wh + (kc * 32 + r) * HC))[c8];
        }
        __syncthreads();
#pragma unroll
        for (int ks = 0; ks < 2; ks++) {
            wmma::fragment<wmma::matrix_a, 16, 16, 16, __half, wmma::row_major> a[2];
#pragma unroll
            for (int mi = 0; mi < 2; mi++)
                wmma::load_matrix_sync(a[mi],
                    &sA[(rt2 * 32 + mi * 16) * LDA + kc * 32 + ks * 16], LDA);
#pragma unroll
            for (int ni = 0; ni < 4; ni++) {
                wmma::fragment<wmma::matrix_b, 16, 16, 16, __half, wmma::row_major> b;
                wmma::load_matrix_sync(b, &sB[ks * 16 * LDB + cg * 64 + ni * 16], LDB);
#pragma unroll
                for (int mi = 0; mi < 2; mi++)
                    wmma::mma_sync(acc[mi][ni], a[mi], b, acc[mi][ni]);
            }
        }
    }

    const int er = lane >> 1;
    const int ec = (lane & 1) * 8;
#pragma unroll
    for (int mi = 0; mi < 2; mi++)
#pragma unroll
    for (int ni = 0; ni < 4; ni++) {
        wmma::store_matrix_sync(&sC[w][0], acc[mi][ni], 24, wmma::mem_row_major);
        __syncwarp();
        float4 v0 = *(float4*)&sC[w][er * 24 + ec];
        float4 v1 = *(float4*)&sC[w][er * 24 + ec + 4];
        int grow = rowBase + rt2 * 32 + mi * 16 + er;  // may hit pad rows (safe)
        uint4 u;
        *(__half2*)&u.x = __floats2half2_rn(v0.x, v0.y);
        *(__half2*)&u.y = __floats2half2_rn(v0.z, v0.w);
        *(__half2*)&u.z = __floats2half2_rn(v1.x, v1.y);
        *(__half2*)&u.w = __floats2half2_rn(v1.z, v1.w);
        *(uint4*)&g_hh[(size_t)grow * HC + cg * 64 + ni * 16 + ec] = u;
        __syncwarp();
    }
}

// ---------------- attention dots from fp32 x: a = x @ u ----------------
__global__ void __launch_bounds__(256) dots_kernel(const float* __restrict__ x) {
    __shared__ float su[1024];           // [sd][h][k]
    int t = threadIdx.x;
#pragma unroll
    for (int i = 0; i < 4; i++) su[t + 256 * i] = g_u[t + 256 * i];
    __syncthreads();

    int node = blockIdx.x * 8 + (t >> 5);
    if (node >= N_NODES) return;
    int lane = t & 31;
    float4 xv = ((const float4*)x)[(size_t)node * 32 + lane];
    int k0 = lane * 4;
    float s[4], d[4];
#pragma unroll
    for (int h = 0; h < 4; h++) {
        float4 us = *(float4*)&su[h * 128 + k0];
        float4 ud = *(float4*)&su[512 + h * 128 + k0];
        s[h] = xv.x * us.x + xv.y * us.y + xv.z * us.z + xv.w * us.w;
        d[h] = xv.x * ud.x + xv.y * ud.y + xv.z * ud.z + xv.w * ud.w;
    }
#pragma unroll
    for (int o = 16; o; o >>= 1) {
#pragma unroll
        for (int h = 0; h < 4; h++) {
            s[h] += __shfl_xor_sync(0xffffffffu, s[h], o);
            d[h] += __shfl_xor_sync(0xffffffffu, d[h], o);
        }
    }
    if (lane == 0) {
        g_asrc[node] = make_float4(s[0], s[1], s[2], s[3]);
        g_adst[node] = make_float4(d[0], d[1], d[2], d[3]);
    }
}

// ---------------- CSR build ----------------
// hist: 4 edges/thread via int4; the atomicAdd return IS the slot rank
// (deg pre-init 1 -> ranks start at 1; slot 0 = self loop).
__global__ void hist_kernel(const int* __restrict__ ei) {
    int t = blockIdx.x * blockDim.x + threadIdx.x;
    if (t >= NE / 4) return;
    int4 d = ((const int4*)(ei + NE))[t];
    unsigned short r0 = 0, r1 = 0, r2 = 0, r3 = 0;
    if ((unsigned)d.x < N_NODES) r0 = (unsigned short)atomicAdd(&g_deg[d.x], 1);
    if ((unsigned)d.y < N_NODES) r1 = (unsigned short)atomicAdd(&g_deg[d.y], 1);
    if ((unsigned)d.z < N_NODES) r2 = (unsigned short)atomicAdd(&g_deg[d.z], 1);
    if ((unsigned)d.w < N_NODES) r3 = (unsigned short)atomicAdd(&g_deg[d.w], 1);
    ushort4 rr; rr.x = r0; rr.y = r1; rr.z = r2; rr.w = r3;
    ((ushort4*)g_rank)[t] = rr;
}

__global__ void __launch_bounds__(1024) scan1_kernel() {
    __shared__ int s[1024];
    int t = threadIdx.x;
    int gi = blockIdx.x * 1024 + t;
    int d = (gi < N_NODES) ? g_deg[gi] : 0;
    int v = d;
    s[t] = v;
    __syncthreads();
#pragma unroll
    for (int o = 1; o < 1024; o <<= 1) {
        int add = (t >= o) ? s[t - o] : 0;
        __syncthreads();
        v += add;
        s[t] = v;
        __syncthreads();
    }
    if (gi < N_NODES) g_off[gi] = v - d;
    if (t == 1023) g_bsum[blockIdx.x] = v;
}

__global__ void scan2_kernel() {
    __shared__ int s[128];
    const int NB = (N_NODES + 1023) / 1024;
    int t = threadIdx.x;
    int d = (t < NB) ? g_bsum[t] : 0;
    int v = d;
    s[t] = v;
    __syncthreads();
#pragma unroll
    for (int o = 1; o < 128; o <<= 1) {
        int add = (t >= o) ? s[t - o] : 0;
        __syncthreads();
        v += add;
        s[t] = v;
        __syncthreads();
    }
    if (t < NB) g_bbase[t] = v - d;
}

__global__ void __launch_bounds__(1024) scan3_kernel() {
    int t = threadIdx.x;
    int gi = blockIdx.x * 1024 + t;
    if (gi < N_NODES) g_off[gi] = g_off[gi] + g_bbase[blockIdx.x];
}

// fill: NO atomics. srcid[off[dst]+rank] = src; self-loop in slot 0.
__global__ void fill_kernel(const int* __restrict__ ei) {
    int t = blockIdx.x * blockDim.x + threadIdx.x;
    if (t < NE / 4) {
        int4 s4 = ((const int4*)ei)[t];
        int4 d4 = ((const int4*)(ei + NE))[t];
        ushort4 rr = ((const ushort4*)g_rank)[t];
        if ((unsigned)d4.x < N_NODES)
            g_srcid[g_off[d4.x] + rr.x] = ((unsigned)s4.x < N_NODES) ? s4.x : 0;
        if ((unsigned)d4.y < N_NODES)
            g_srcid[g_off[d4.y] + rr.y] = ((unsigned)s4.y < N_NODES) ? s4.y : 0;
        if ((unsigned)d4.z < N_NODES)
            g_srcid[g_off[d4.z] + rr.z] = ((unsigned)s4.z < N_NODES) ? s4.z : 0;
        if ((unsigned)d4.w < N_NODES)
            g_srcid[g_off[d4.w] + rr.w] = ((unsigned)s4.w < N_NODES) ? s4.w : 0;
    } else {
        int n = t - NE / 4;
        if (n < N_NODES) g_srcid[g_off[n]] = n;     // self loop, slot 0
    }
}

// ---------------- SINGLE-PASS aggregation: one warp per dst node -----------
// Edge-batched: 32 edges per coalesced srcid load; sub-batches of 8 where
// lane 4j+h computes exp for (edge j, head h) -> 1 MUFU round per 8 edges.
// h gather unchanged: 1 LDG.128 per edge per lane (the only real traffic).
__device__ __forceinline__ void acc8(float* acc, uint4 hv, float wm) {
    float2 f0 = __half22float2(*(__half2*)&hv.x);
    float2 f1 = __half22float2(*(__half2*)&hv.y);
    float2 f2 = __half22float2(*(__half2*)&hv.z);
    float2 f3 = __half22float2(*(__half2*)&hv.w);
    acc[0] = fmaf(f0.x, wm, acc[0]); acc[1] = fmaf(f0.y, wm, acc[1]);
    acc[2] = fmaf(f1.x, wm, acc[2]); acc[3] = fmaf(f1.y, wm, acc[3]);
    acc[4] = fmaf(f2.x, wm, acc[4]); acc[5] = fmaf(f2.y, wm, acc[5]);
    acc[6] = fmaf(f3.x, wm, acc[6]); acc[7] = fmaf(f3.y, wm, acc[7]);
}

__global__ void __launch_bounds__(256) agg_kernel(const float* __restrict__ bias,
                                                  float* __restrict__ out) {
    const int lane = threadIdx.x & 31;
    const int wpb = blockDim.x >> 5;
    const int wib = threadIdx.x >> 5;
    const int warp = blockIdx.x * wpb + wib;
    const int nwarps = gridDim.x * wpb;
    const int hsel = lane & 3;       // head this lane computes exp for
    const int hmy = lane >> 3;       // head of this lane's 8 channels

    float bnsum[8], bnsq[8], biasv[8];
#pragma unroll
    for (int q = 0; q < 8; q++) {
        bnsum[q] = 0.f; bnsq[q] = 0.f;
        biasv[q] = bias[lane * 8 + q];
    }

    for (int node = warp; node < N_NODES; node += nwarps) {
        const int beg = g_off[node];
        const int end = g_off[node + 1];
        const float adv = selh(g_adst[node], hsel);

        float wsum = 0.f;                 // partial denom for head hsel
        float acc[8];
#pragma unroll
        for (int q = 0; q < 8; q++) acc[q] = 0.f;

        for (int e32 = beg; e32 < end; e32 += 32) {
            int cnt = end - e32; if (cnt > 32) cnt = 32;
            int sv = (lane < cnt) ? g_srcid[e32 + lane] : 0;
#pragma unroll
            for (int sub = 0; sub < 4; sub++) {
                if (sub * 8 >= cnt) break;
                int myj = sub * 8 + (lane >> 2);      // my edge in batch
                int sj = __shfl_sync(0xffffffffu, sv, myj);
                float av = ((const float*)g_asrc)[sj * 4 + hsel];
                float wv = (myj < cnt) ? __expf(lrelu(av + adv)) : 0.f;
                wsum += wv;
#pragma unroll
                for (int j = 0; j < 8; j++) {
                    float wm = __shfl_sync(0xffffffffu, wv, j * 4 + hmy);
                    int sb = __shfl_sync(0xffffffffu, sv, sub * 8 + j);
                    uint4 hv = ((const uint4*)(g_hh + (size_t)sb * HC))[lane];
                    acc8(acc, hv, wm);               // wm==0 for padded edges
                }
            }
        }

        // denom: sum lanes sharing hsel (xor 4,8,16)
#pragma unroll
        for (int o = 4; o < 32; o <<= 1)
            wsum += __shfl_xor_sync(0xffffffffu, wsum, o);
        float inv = 1.f / (wsum + 1e-16f);
        float invm = __shfl_sync(0xffffffffu, inv, hmy);  // lane hmy holds head hmy

        float v[8];
#pragma unroll
        for (int q = 0; q < 8; q++) {
            v[q] = fmaf(acc[q], invm, biasv[q]);
            bnsum[q] += v[q];
            bnsq[q] = fmaf(v[q], v[q], bnsq[q]);
        }
        float4* op4 = (float4*)(out + (size_t)node * HC);
        op4[lane * 2]     = make_float4(v[0], v[1], v[2], v[3]);
        op4[lane * 2 + 1] = make_float4(v[4], v[5], v[6], v[7]);
    }

    // ---- block-level BN partial reduction (channel c = lane*8+q) ----
    __shared__ float s_sum[8][HC];
    __shared__ float s_sq[8][HC];
    {
        float4* ss = (float4*)s_sum[wib];
        float4* sq = (float4*)s_sq[wib];
        ss[lane * 2]     = make_float4(bnsum[0], bnsum[1], bnsum[2], bnsum[3]);
        ss[lane * 2 + 1] = make_float4(bnsum[4], bnsum[5], bnsum[6], bnsum[7]);
        sq[lane * 2]     = make_float4(bnsq[0], bnsq[1], bnsq[2], bnsq[3]);
        sq[lane * 2 + 1] = make_float4(bnsq[4], bnsq[5], bnsq[6], bnsq[7]);
    }
    __syncthreads();
    {
        int c = threadIdx.x;
        float ts = 0.f, tq = 0.f;
#pragma unroll
        for (int w = 0; w < 8; w++) { ts += s_sum[w][c]; tq += s_sq[w][c]; }
        atomicAdd(&g_bnsum[c], ts);
        atomicAdd(&g_bnsq[c], tq);
    }
}

// ---------------- BatchNorm + ELU epilogue (float4) ----------------
__global__ void bn_elu_kernel(const float* __restrict__ gamma,
                              const float* __restrict__ beta,
                              float* __restrict__ out) {
    int idx = blockIdx.x * blockDim.x + threadIdx.x;     // over N*HC/4
    if (idx >= N_NODES * (HC / 4)) return;
    int c0 = (idx & 63) * 4;
    const float invN = 1.f / (float)N_NODES;
    float4 v = ((const float4*)out)[idx];
    float r[4] = {v.x, v.y, v.z, v.w};
#pragma unroll
    for (int q = 0; q < 4; q++) {
        int c = c0 + q;
        float mean = g_bnsum[c] * invN;
        float var = g_bnsq[c] * invN - mean * mean;
        float y = gamma[c] * (r[q] - mean) * rsqrtf(var + BN_EPS) + beta[c];
        r[q] = y > 0.f ? y : expm1f(y);
    }
    ((float4*)out)[idx] = make_float4(r[0], r[1], r[2], r[3]);
}

// ---------------- launch ----------------
extern "C" void kernel_launch(void* const* d_in, const int* in_sizes, int n_in,
                              void* d_out, int out_size) {
    const float* x       = (const float*)d_in[0];
    const int*   ei      = (const int*)d_in[1];     // JAX x64 disabled => int32
    const float* W       = (const float*)d_in[2];
    const float* att_src = (const float*)d_in[3];
    const float* att_dst = (const float*)d_in[4];
    const float* bias    = (const float*)d_in[5];
    const float* gamma   = (const float*)d_in[6];
    const float* beta    = (const float*)d_in[7];
    float* out = (float*)d_out;

    prep_kernel<<<(N_NODES + 255) / 256, 256>>>(W, att_src, att_dst);
    gemm_kernel<<<(N_NODES + 63) / 64, 256>>>(x);
    dots_kernel<<<(N_NODES + 7) / 8, 256>>>(x);
    hist_kernel<<<(NE / 4 + 255) / 256, 256>>>(ei);
    scan1_kernel<<<(N_NODES + 1023) / 1024, 1024>>>();
    scan2_kernel<<<1, 128>>>();
    scan3_kernel<<<(N_NODES + 1023) / 1024, 1024>>>();
    fill_kernel<<<(NE / 4 + N_NODES + 255) / 256, 256>>>(ei);
    agg_kernel<<<2048, 256>>>(bias, out);
    bn_elu_kernel<<<(N_NODES * (HC / 4) + 255) / 256, 256>>>(gamma, beta, out);
}